// round 6
// baseline (speedup 1.0000x reference)
#include <cuda_runtime.h>
#include <cuda_bf16.h>
#include <stdint.h>

#define BB 256
#define TT 512
#define HH 512
#define II 256
#define BH 131072
#define NCTA 128
#define NTHR 256

// SMEM: A dbl-buf 2 x (16K hi + 16K lo) = 64K, then U hi 64K, U lo 64K
#define SO_AL 16384
#define AB1   32768
#define SO_UH 65536
#define SO_UL 131072
#define SMEM_TOT 196608

// ---------------- device globals ----------------
__device__ __align__(16) __nv_bfloat16 g_Ut_hi[2048 * 512];
__device__ __align__(16) __nv_bfloat16 g_Ut_lo[2048 * 512];
__device__ __align__(16) __nv_bfloat16 g_Wt_hi[2048 * 256];
__device__ __align__(16) __nv_bfloat16 g_Wt_lo[2048 * 256];
__device__ __align__(16) __nv_bfloat16 g_x0_hi[256 * 256];
__device__ __align__(16) __nv_bfloat16 g_x0_lo[256 * 256];
__device__ __align__(16) __nv_bfloat16 g_ahi[2][BH];
__device__ __align__(16) __nv_bfloat16 g_alo[2][BH];
__device__ unsigned int g_flag[4][32];   // [mtile][ntile] = steps produced

// ---------------- helpers ----------------
__device__ __forceinline__ uint32_t smem_u32(const void *p) {
    uint32_t a;
    asm("{ .reg .u64 t; cvta.to.shared.u64 t, %1; cvt.u32.u64 %0, t; }"
        : "=r"(a) : "l"(p));
    return a;
}
__device__ __forceinline__ void cpa16(uint32_t dst, const void *src) {
    asm volatile("cp.async.cg.shared.global [%0], [%1], 16;"
                 :: "r"(dst), "l"(__cvta_generic_to_global(src)) : "memory");
}
#define CP_COMMIT asm volatile("cp.async.commit_group;" ::: "memory")

__device__ __forceinline__ unsigned ldacq(const unsigned *p) {
    unsigned v;
    asm volatile("ld.acquire.gpu.global.u32 %0, [%1];"
                 : "=r"(v) : "l"(__cvta_generic_to_global((void *)p)) : "memory");
    return v;
}
__device__ __forceinline__ void ldsm4(uint32_t addr, uint32_t r[4]) {
    asm volatile("ldmatrix.sync.aligned.m8n8.x4.shared.b16 {%0,%1,%2,%3}, [%4];"
                 : "=r"(r[0]), "=r"(r[1]), "=r"(r[2]), "=r"(r[3]) : "r"(addr));
}
__device__ __forceinline__ void mmabf(float c[4], const uint32_t a[4],
                                      uint32_t b0, uint32_t b1) {
    asm volatile(
        "mma.sync.aligned.m16n8k16.row.col.f32.bf16.bf16.f32 "
        "{%0,%1,%2,%3}, {%4,%5,%6,%7}, {%8,%9}, {%0,%1,%2,%3};"
        : "+f"(c[0]), "+f"(c[1]), "+f"(c[2]), "+f"(c[3])
        : "r"(a[0]), "r"(a[1]), "r"(a[2]), "r"(a[3]), "r"(b0), "r"(b1));
}
__device__ __forceinline__ float sigf(float x) {
    return __fdividef(1.0f, 1.0f + __expf(-x));
}
__device__ __forceinline__ float tanhfast(float x) {
    return 1.0f - __fdividef(2.0f, __expf(2.0f * x) + 1.0f);
}

// ---------------- prep: permute cols (gate-interleave) + bf16 split ----------------
__global__ void prep_kernel(const float *__restrict__ rnn,
                            const float *__restrict__ h0,
                            const float *__restrict__ Ww,
                            const float *__restrict__ Uw)
{
    if (blockIdx.x == 0 && threadIdx.x < 128)
        ((unsigned *)g_flag)[threadIdx.x] = 0u;
    const long TU = 512L * 2048, TW = 256L * 2048, TX = 256L * 256, TH = 256L * 512;
    const long TOT = TU + TW + TX + TH;
    for (long i = (long)blockIdx.x * blockDim.x + threadIdx.x; i < TOT;
         i += (long)gridDim.x * blockDim.x) {
        if (i < TU) {
            long k = i >> 11;
            int n = (int)(i & 2047);
            int p = ((n & 511) << 2) | (n >> 9);   // h*4 + gate
            float v = Uw[i];
            __nv_bfloat16 hi = __float2bfloat16_rn(v);
            g_Ut_hi[(long)p * 512 + k] = hi;
            g_Ut_lo[(long)p * 512 + k] = __float2bfloat16_rn(v - __bfloat162float(hi));
        } else if (i < TU + TW) {
            long j = i - TU;
            long k = j >> 11;
            int n = (int)(j & 2047);
            int p = ((n & 511) << 2) | (n >> 9);
            float v = Ww[j];
            __nv_bfloat16 hi = __float2bfloat16_rn(v);
            g_Wt_hi[(long)p * 256 + k] = hi;
            g_Wt_lo[(long)p * 256 + k] = __float2bfloat16_rn(v - __bfloat162float(hi));
        } else if (i < TU + TW + TX) {
            long j = i - TU - TW;
            float v = rnn[j];
            __nv_bfloat16 hi = __float2bfloat16_rn(v);
            g_x0_hi[j] = hi;
            g_x0_lo[j] = __float2bfloat16_rn(v - __bfloat162float(hi));
        } else {
            long j = i - TU - TW - TX;
            float v = h0[j];
            __nv_bfloat16 hi = __float2bfloat16_rn(v);
            g_ahi[0][j] = hi;
            g_alo[0][j] = __float2bfloat16_rn(v - __bfloat162float(hi));
        }
    }
}

// ---------------- GEMM: C[64x64] += A[64 x NC*128] * B(smem)^T, split-bf16 3-pass ----
// KC = 128. A buf: 64 rows x 256B pitch (hi), lo at +SO_AL; buffers at 0 / AB1.
template <int NC, int BPITCH, bool FLAGS>
__device__ __forceinline__ void run_gemm(
    const __nv_bfloat16 *__restrict__ gh, const __nv_bfloat16 *__restrict__ gl,
    int ldk, int m0, int mtile, unsigned need,
    uint32_t smb, int tid, int lane, int wm, int wn, float C[4][4])
{
    // chunk 0: wait producers, then prefetch
    if (FLAGS && need) {
        const unsigned *fp = &g_flag[mtile][tid & 7];
        while (ldacq(fp) < need) {}
    }
    __syncthreads();   // flag visibility + A-buffer reuse guard
    {
#pragma unroll
        for (int i = 0; i < 4; ++i) {
            int u = tid + 256 * i, m = u >> 4, kg = u & 15;
            size_t go = (size_t)(m0 + m) * ldk + kg * 8;
            uint32_t d = (uint32_t)(m * 256 + ((kg * 16) ^ ((m & 7) << 4)));
            cpa16(smb + d, gh + go);
            cpa16(smb + d + SO_AL, gl + go);
        }
        CP_COMMIT;
    }
    for (int kc = 0; kc < NC; ++kc) {
        if (kc + 1 < NC) {
            if (FLAGS && need) {
                const unsigned *fp = &g_flag[mtile][(kc + 1) * 8 + (tid & 7)];
                while (ldacq(fp) < need) {}
            }
            __syncthreads();
#pragma unroll
            for (int i = 0; i < 4; ++i) {
                int u = tid + 256 * i, m = u >> 4, kg = u & 15;
                size_t go = (size_t)(m0 + m) * ldk + (kc + 1) * 128 + kg * 8;
                uint32_t d = (uint32_t)(((kc + 1) & 1) * AB1 + m * 256 +
                                        ((kg * 16) ^ ((m & 7) << 4)));
                cpa16(smb + d, gh + go);
                cpa16(smb + d + SO_AL, gl + go);
            }
            CP_COMMIT;
            asm volatile("cp.async.wait_group 1;" ::: "memory");
        } else {
            asm volatile("cp.async.wait_group 0;" ::: "memory");
        }
        __syncthreads();
        uint32_t ab = smb + (kc & 1) * AB1;
#pragma unroll
        for (int sub = 0; sub < 8; ++sub) {
            uint32_t ahr[4], alr[4];
            {
                int mat = lane >> 3, rr = lane & 7;
                int mloc = wm * 16 + ((mat & 1) << 3) + rr;
                int kb = sub * 32 + ((mat >> 1) << 4);
                uint32_t off = mloc * 256 + (kb ^ ((mloc & 7) << 4));
                ldsm4(ab + off, ahr);
                ldsm4(ab + SO_AL + off, alr);
            }
            uint32_t bhf[8], blf[8];
            const int kg2 = (kc * 128 + sub * 16) * 2;
#pragma unroll
            for (int half = 0; half < 2; ++half) {
                int mat = lane >> 3, rr = lane & 7;
                int nloc = wn * 32 + half * 16 + ((mat >> 1) << 3) + rr;
                int kb = kg2 + ((mat & 1) << 4);
                uint32_t off = nloc * BPITCH + (kb ^ ((nloc & 7) << 4));
                ldsm4(smb + SO_UH + off, &bhf[half * 4]);
                ldsm4(smb + SO_UL + off, &blf[half * 4]);
            }
#pragma unroll
            for (int nb = 0; nb < 4; ++nb) {
                mmabf(C[nb], ahr, bhf[nb * 2], bhf[nb * 2 + 1]);
                mmabf(C[nb], alr, bhf[nb * 2], bhf[nb * 2 + 1]);
                mmabf(C[nb], ahr, blf[nb * 2], blf[nb * 2 + 1]);
            }
        }
    }
}

// ---------------- main persistent kernel ----------------
__global__ void __launch_bounds__(NTHR, 1) lstm_mma(
    const int *__restrict__ bsz, const float *__restrict__ h0in,
    const float *__restrict__ c0in, const float *__restrict__ taup,
    const float *__restrict__ Wb, float *__restrict__ out)
{
    extern __shared__ char sm[];
    const uint32_t smb = smem_u32(sm);
    const int tid = threadIdx.x, cta = blockIdx.x;
    const int lane = tid & 31, wid = tid >> 5;
    const int wm = wid & 3, wn = wid >> 2;
    const int mtile = cta & 3, ntile = cta >> 2;
    const int m0 = mtile * 64;
    const float tauv = __ldg(taup);

    const int cc = lane & 3;
    const int hbash = ntile * 16 + wn * 8 + (cc >> 1);
    const int mg0 = m0 + wm * 16 + (lane >> 2);

    // ---- fill W into U slots (pitch 512B), compute pre via MMA ----
    {
        char *p = sm;
#pragma unroll
        for (int i = 0; i < 8; ++i) {
            int u = tid + 256 * i, n = u >> 5, kg = u & 31;
            uint32_t d = n * 512 + ((kg * 16) ^ ((n & 7) << 4));
            *(uint4 *)(p + SO_UH + d) =
                *(const uint4 *)(g_Wt_hi + (size_t)(ntile * 64 + n) * 256 + kg * 8);
            *(uint4 *)(p + SO_UL + d) =
                *(const uint4 *)(g_Wt_lo + (size_t)(ntile * 64 + n) * 256 + kg * 8);
        }
    }
    __syncthreads();

    float C[4][4];
#pragma unroll
    for (int a = 0; a < 4; ++a)
#pragma unroll
        for (int r = 0; r < 4; ++r) C[a][r] = 0.0f;
    run_gemm<2, 512, false>(g_x0_hi, g_x0_lo, II, m0, mtile, 0u,
                            smb, tid, lane, wm, wn, C);

    float pre[4][4];
#pragma unroll
    for (int nb = 0; nb < 4; ++nb)
#pragma unroll
        for (int r = 0; r < 4; ++r) {
            int gate = (cc * 2 + (r & 1)) & 3;
            int hg = ntile * 16 + wn * 8 + nb * 2 + (cc >> 1);
            pre[nb][r] = C[nb][r] + __ldg(Wb + gate * 512 + hg);
        }
    __syncthreads();

    // ---- fill U resident (pitch 1024B) ----
    {
        char *p = sm;
#pragma unroll
        for (int i = 0; i < 16; ++i) {
            int u = tid + 256 * i, n = u >> 6, kg = u & 63;
            uint32_t d = n * 1024 + ((kg * 16) ^ ((n & 7) << 4));
            *(uint4 *)(p + SO_UH + d) =
                *(const uint4 *)(g_Ut_hi + (size_t)(ntile * 64 + n) * 512 + kg * 8);
            *(uint4 *)(p + SO_UL + d) =
                *(const uint4 *)(g_Ut_lo + (size_t)(ntile * 64 + n) * 512 + kg * 8);
        }
    }
    __syncthreads();

    // ---- per-thread cell states (4 cells: [p][mh]) ----
    float cs[2][2], hs[2][2];
#pragma unroll
    for (int p = 0; p < 2; ++p) {
        int nb = (lane & 1) ? 2 + p : p;
        int hg = hbash + nb * 2;
#pragma unroll
        for (int mh = 0; mh < 2; ++mh) {
            int mg = mg0 + mh * 8;
            cs[p][mh] = __ldg(c0in + (size_t)mg * 512 + hg);
            hs[p][mh] = __ldg(h0in + (size_t)mg * 512 + hg);
        }
    }

    // ---- time loop (no grid barrier: producer/consumer flags) ----
    for (int t = 0; t < TT; ++t) {
#pragma unroll
        for (int a = 0; a < 4; ++a)
#pragma unroll
            for (int r = 0; r < 4; ++r) C[a][r] = 0.0f;
        run_gemm<4, 1024, true>(g_ahi[t & 1], g_alo[t & 1], HH, m0, mtile,
                                (unsigned)t, smb, tid, lane, wm, wn, C);

        const int bs = __ldg(bsz + t);

        // gate sums = C + pre; exchange complementary gate pairs with lane^1
        float own[2][4], R[2][4];
#pragma unroll
        for (int p = 0; p < 2; ++p)
#pragma unroll
            for (int r = 0; r < 4; ++r) {
                float lo2 = C[p][r] + pre[p][r];
                float hi2 = C[2 + p][r] + pre[2 + p][r];
                own[p][r] = (lane & 1) ? hi2 : lo2;
                float send = (lane & 1) ? lo2 : hi2;
                R[p][r] = __shfl_xor_sync(0xffffffffu, send, 1);
            }

#pragma unroll
        for (int p = 0; p < 2; ++p) {
            int nb = (lane & 1) ? 2 + p : p;
            int hg = hbash + nb * 2;
#pragma unroll
            for (int mh = 0; mh < 2; ++mh) {
                float vi, vf, vg, vo;
                if (lane & 1) {
                    vg = own[p][mh * 2]; vo = own[p][mh * 2 + 1];
                    vi = R[p][mh * 2];   vf = R[p][mh * 2 + 1];
                } else {
                    vi = own[p][mh * 2]; vf = own[p][mh * 2 + 1];
                    vg = R[p][mh * 2];   vo = R[p][mh * 2 + 1];
                }
                int mg = mg0 + mh * 8;
                float cn = sigf(vf) * cs[p][mh] + sigf(vi) * tanhfast(vg);
                float hn = sigf(vo) * tanhfast(cn);
                bool act = (mg < bs);
                float o = act ? hn : 0.0f;
                if (act) { cs[p][mh] = cn; hs[p][mh] = hn; }
                out[(size_t)t * BH + (size_t)mg * 512 + hg] = o;
            }
        }

        if (t < TT - 1) {
            // drift on h dims 0,1 (owned by ntile 0, wn 0, nb 0 → lanes cc 0 and 2)
            if (ntile == 0 && wn == 0) {
#pragma unroll
                for (int mh = 0; mh < 2; ++mh) {
                    float mine = hs[0][mh];
                    float oth = __shfl_xor_sync(0xffffffffu, mine, 2);
                    if (!(lane & 1)) {
                        if (cc == 0)
                            hs[0][mh] = mine + tauv * (1.5f * mine + oth * (1.0f / 1.5f));
                        else if (cc == 2)
                            hs[0][mh] = mine - tauv * (1.5f * oth);
                    }
                }
            }
            __nv_bfloat16 *dh = g_ahi[(t + 1) & 1];
            __nv_bfloat16 *dl = g_alo[(t + 1) & 1];
#pragma unroll
            for (int p = 0; p < 2; ++p) {
                int nb = (lane & 1) ? 2 + p : p;
                int hg = hbash + nb * 2;
#pragma unroll
                for (int mh = 0; mh < 2; ++mh) {
                    int mg = mg0 + mh * 8;
                    float v = hs[p][mh];
                    __nv_bfloat16 bh16 = __float2bfloat16_rn(v);
                    dh[(size_t)mg * 512 + hg] = bh16;
                    dl[(size_t)mg * 512 + hg] =
                        __float2bfloat16_rn(v - __bfloat162float(bh16));
                }
            }
            __threadfence();
            __syncthreads();
            if (tid == 0)
                *(volatile unsigned *)&g_flag[mtile][ntile] = (unsigned)(t + 1);
        }
    }

    // ---- final h, c ----
    const size_t ofs = (size_t)TT * BH;
#pragma unroll
    for (int p = 0; p < 2; ++p) {
        int nb = (lane & 1) ? 2 + p : p;
        int hg = hbash + nb * 2;
#pragma unroll
        for (int mh = 0; mh < 2; ++mh) {
            int mg = mg0 + mh * 8;
            out[ofs + (size_t)mg * 512 + hg] = hs[p][mh];
            out[ofs + BH + (size_t)mg * 512 + hg] = cs[p][mh];
        }
    }
}

extern "C" void kernel_launch(void *const *d_in, const int *in_sizes, int n_in,
                              void *d_out, int out_size)
{
    const float *rnn = (const float *)d_in[0];
    const int *bsz = (const int *)d_in[1];
    const float *h0 = (const float *)d_in[2];
    const float *c0 = (const float *)d_in[3];
    const float *tau = (const float *)d_in[4];
    const float *Ww = (const float *)d_in[5];
    const float *Wb = (const float *)d_in[6];
    const float *Uw = (const float *)d_in[7];
    float *out = (float *)d_out;

    cudaFuncSetAttribute(lstm_mma, cudaFuncAttributeMaxDynamicSharedMemorySize,
                         SMEM_TOT);
    prep_kernel<<<512, 256>>>(rnn, h0, Ww, Uw);
    lstm_mma<<<NCTA, NTHR, SMEM_TOT>>>(bsz, h0, c0, tau, Wb, out);
}

// round 7
// speedup vs baseline: 1.5138x; 1.5138x over previous
#include <cuda_runtime.h>
#include <cuda_bf16.h>
#include <stdint.h>

#define BB 256
#define TT 512
#define HH 512
#define II 256
#define BH 131072
#define NCTA 128
#define NTHR 256

// SMEM: A dbl-buf 2 x (16K hi + 16K lo) = 64K, then U hi 64K, U lo 64K
#define SO_AL 16384
#define AB1   32768
#define SO_UH 65536
#define SO_UL 131072
#define SMEM_TOT 196608

// ---------------- device globals ----------------
__device__ __align__(16) __nv_bfloat16 g_Ut_hi[2048 * 512];
__device__ __align__(16) __nv_bfloat16 g_Ut_lo[2048 * 512];
__device__ __align__(16) __nv_bfloat16 g_Wt_hi[2048 * 256];
__device__ __align__(16) __nv_bfloat16 g_Wt_lo[2048 * 256];
__device__ __align__(16) __nv_bfloat16 g_x0_hi[256 * 256];
__device__ __align__(16) __nv_bfloat16 g_x0_lo[256 * 256];
__device__ __align__(16) __nv_bfloat16 g_ahi[2][BH];
__device__ __align__(16) __nv_bfloat16 g_alo[2][BH];
__device__ unsigned int g_arr;   // monotone arrival counter (reset by prep)

// ---------------- helpers ----------------
__device__ __forceinline__ uint32_t smem_u32(const void *p) {
    uint32_t a;
    asm("{ .reg .u64 t; cvta.to.shared.u64 t, %1; cvt.u32.u64 %0, t; }"
        : "=r"(a) : "l"(p));
    return a;
}
__device__ __forceinline__ void cpa16(uint32_t dst, const void *src) {
    asm volatile("cp.async.cg.shared.global [%0], [%1], 16;"
                 :: "r"(dst), "l"(__cvta_generic_to_global(src)) : "memory");
}
#define CP_COMMIT asm volatile("cp.async.commit_group;" ::: "memory")

__device__ __forceinline__ unsigned ldacq(const unsigned *p) {
    unsigned v;
    asm volatile("ld.acquire.gpu.global.u32 %0, [%1];"
                 : "=r"(v) : "l"(__cvta_generic_to_global((void *)p)) : "memory");
    return v;
}
__device__ __forceinline__ void ldsm4(uint32_t addr, uint32_t r[4]) {
    asm volatile("ldmatrix.sync.aligned.m8n8.x4.shared.b16 {%0,%1,%2,%3}, [%4];"
                 : "=r"(r[0]), "=r"(r[1]), "=r"(r[2]), "=r"(r[3]) : "r"(addr));
}
__device__ __forceinline__ void mmabf(float c[4], const uint32_t a[4],
                                      uint32_t b0, uint32_t b1) {
    asm volatile(
        "mma.sync.aligned.m16n8k16.row.col.f32.bf16.bf16.f32 "
        "{%0,%1,%2,%3}, {%4,%5,%6,%7}, {%8,%9}, {%0,%1,%2,%3};"
        : "+f"(c[0]), "+f"(c[1]), "+f"(c[2]), "+f"(c[3])
        : "r"(a[0]), "r"(a[1]), "r"(a[2]), "r"(a[3]), "r"(b0), "r"(b1));
}
__device__ __forceinline__ float sigf(float x) {
    return __fdividef(1.0f, 1.0f + __expf(-x));
}
__device__ __forceinline__ float tanhfast(float x) {
    return 1.0f - __fdividef(2.0f, __expf(2.0f * x) + 1.0f);
}

// ---------------- prep: permute cols (gate-interleave) + bf16 split ----------------
__global__ void prep_kernel(const float *__restrict__ rnn,
                            const float *__restrict__ h0,
                            const float *__restrict__ Ww,
                            const float *__restrict__ Uw)
{
    if (blockIdx.x == 0 && threadIdx.x == 0) g_arr = 0u;
    const long TU = 512L * 2048, TW = 256L * 2048, TX = 256L * 256, TH = 256L * 512;
    const long TOT = TU + TW + TX + TH;
    for (long i = (long)blockIdx.x * blockDim.x + threadIdx.x; i < TOT;
         i += (long)gridDim.x * blockDim.x) {
        if (i < TU) {
            long k = i >> 11;
            int n = (int)(i & 2047);
            int p = ((n & 511) << 2) | (n >> 9);   // h*4 + gate
            float v = Uw[i];
            __nv_bfloat16 hi = __float2bfloat16_rn(v);
            g_Ut_hi[(long)p * 512 + k] = hi;
            g_Ut_lo[(long)p * 512 + k] = __float2bfloat16_rn(v - __bfloat162float(hi));
        } else if (i < TU + TW) {
            long j = i - TU;
            long k = j >> 11;
            int n = (int)(j & 2047);
            int p = ((n & 511) << 2) | (n >> 9);
            float v = Ww[j];
            __nv_bfloat16 hi = __float2bfloat16_rn(v);
            g_Wt_hi[(long)p * 256 + k] = hi;
            g_Wt_lo[(long)p * 256 + k] = __float2bfloat16_rn(v - __bfloat162float(hi));
        } else if (i < TU + TW + TX) {
            long j = i - TU - TW;
            float v = rnn[j];
            __nv_bfloat16 hi = __float2bfloat16_rn(v);
            g_x0_hi[j] = hi;
            g_x0_lo[j] = __float2bfloat16_rn(v - __bfloat162float(hi));
        } else {
            long j = i - TU - TW - TX;
            float v = h0[j];
            __nv_bfloat16 hi = __float2bfloat16_rn(v);
            g_ahi[0][j] = hi;
            g_alo[0][j] = __float2bfloat16_rn(v - __bfloat162float(hi));
        }
    }
}

// ---------------- GEMM: C[64x64] += A[64 x NC*128] * B(smem)^T, split-bf16 3-pass ----
// KC = 128. A buf: 64 rows x 256B pitch (hi), lo at +SO_AL; buffers at 0 / AB1.
template <int NC, int BPITCH>
__device__ __forceinline__ void run_gemm(
    const __nv_bfloat16 *__restrict__ gh, const __nv_bfloat16 *__restrict__ gl,
    int ldk, int m0, uint32_t smb, int tid, int lane, int wm, int wn, float C[4][4])
{
    __syncthreads();   // A-buffer reuse guard across calls
    {
#pragma unroll
        for (int i = 0; i < 4; ++i) {
            int u = tid + 256 * i, m = u >> 4, kg = u & 15;
            size_t go = (size_t)(m0 + m) * ldk + kg * 8;
            uint32_t d = (uint32_t)(m * 256 + ((kg * 16) ^ ((m & 7) << 4)));
            cpa16(smb + d, gh + go);
            cpa16(smb + d + SO_AL, gl + go);
        }
        CP_COMMIT;
    }
    for (int kc = 0; kc < NC; ++kc) {
        if (kc + 1 < NC) {
            __syncthreads();   // all warps done with the buffer we are about to fill
#pragma unroll
            for (int i = 0; i < 4; ++i) {
                int u = tid + 256 * i, m = u >> 4, kg = u & 15;
                size_t go = (size_t)(m0 + m) * ldk + (kc + 1) * 128 + kg * 8;
                uint32_t d = (uint32_t)(((kc + 1) & 1) * AB1 + m * 256 +
                                        ((kg * 16) ^ ((m & 7) << 4)));
                cpa16(smb + d, gh + go);
                cpa16(smb + d + SO_AL, gl + go);
            }
            CP_COMMIT;
            asm volatile("cp.async.wait_group 1;" ::: "memory");
        } else {
            asm volatile("cp.async.wait_group 0;" ::: "memory");
        }
        __syncthreads();
        uint32_t ab = smb + (kc & 1) * AB1;
#pragma unroll
        for (int sub = 0; sub < 8; ++sub) {
            uint32_t ahr[4], alr[4];
            {
                int mat = lane >> 3, rr = lane & 7;
                int mloc = wm * 16 + ((mat & 1) << 3) + rr;
                int kb = sub * 32 + ((mat >> 1) << 4);
                uint32_t off = mloc * 256 + (kb ^ ((mloc & 7) << 4));
                ldsm4(ab + off, ahr);
                ldsm4(ab + SO_AL + off, alr);
            }
            uint32_t bhf[8], blf[8];
            const int kg2 = (kc * 128 + sub * 16) * 2;
#pragma unroll
            for (int half = 0; half < 2; ++half) {
                int mat = lane >> 3, rr = lane & 7;
                int nloc = wn * 32 + half * 16 + ((mat >> 1) << 3) + rr;
                int kb = kg2 + ((mat & 1) << 4);
                uint32_t off = nloc * BPITCH + (kb ^ ((nloc & 7) << 4));
                ldsm4(smb + SO_UH + off, &bhf[half * 4]);
                ldsm4(smb + SO_UL + off, &blf[half * 4]);
            }
#pragma unroll
            for (int nb = 0; nb < 4; ++nb) {
                mmabf(C[nb], ahr, bhf[nb * 2], bhf[nb * 2 + 1]);
                mmabf(C[nb], alr, bhf[nb * 2], bhf[nb * 2 + 1]);
                mmabf(C[nb], ahr, blf[nb * 2], blf[nb * 2 + 1]);
            }
        }
    }
}

// ---------------- main persistent kernel ----------------
__global__ void __launch_bounds__(NTHR, 1) lstm_mma(
    const int *__restrict__ bsz, const float *__restrict__ h0in,
    const float *__restrict__ c0in, const float *__restrict__ taup,
    const float *__restrict__ Wb, float *__restrict__ out)
{
    extern __shared__ char sm[];
    const uint32_t smb = smem_u32(sm);
    const int tid = threadIdx.x, cta = blockIdx.x;
    const int lane = tid & 31, wid = tid >> 5;
    const int wm = wid & 3, wn = wid >> 2;
    const int mtile = cta & 3, ntile = cta >> 2;
    const int m0 = mtile * 64;
    const float tauv = __ldg(taup);

    const int cc = lane & 3;
    const int hbash = ntile * 16 + wn * 8 + (cc >> 1);
    const int mg0 = m0 + wm * 16 + (lane >> 2);

    // ---- fill W into U slots (pitch 512B), compute pre via MMA ----
    {
        char *p = sm;
#pragma unroll
        for (int i = 0; i < 8; ++i) {
            int u = tid + 256 * i, n = u >> 5, kg = u & 31;
            uint32_t d = n * 512 + ((kg * 16) ^ ((n & 7) << 4));
            *(uint4 *)(p + SO_UH + d) =
                *(const uint4 *)(g_Wt_hi + (size_t)(ntile * 64 + n) * 256 + kg * 8);
            *(uint4 *)(p + SO_UL + d) =
                *(const uint4 *)(g_Wt_lo + (size_t)(ntile * 64 + n) * 256 + kg * 8);
        }
    }
    __syncthreads();

    float C[4][4];
#pragma unroll
    for (int a = 0; a < 4; ++a)
#pragma unroll
        for (int r = 0; r < 4; ++r) C[a][r] = 0.0f;
    run_gemm<2, 512>(g_x0_hi, g_x0_lo, II, m0, smb, tid, lane, wm, wn, C);

    float pre[4][4];
#pragma unroll
    for (int nb = 0; nb < 4; ++nb)
#pragma unroll
        for (int r = 0; r < 4; ++r) {
            int gate = (cc * 2 + (r & 1)) & 3;
            int hg = ntile * 16 + wn * 8 + nb * 2 + (cc >> 1);
            pre[nb][r] = C[nb][r] + __ldg(Wb + gate * 512 + hg);
        }
    __syncthreads();

    // ---- fill U resident (pitch 1024B) ----
    {
        char *p = sm;
#pragma unroll
        for (int i = 0; i < 16; ++i) {
            int u = tid + 256 * i, n = u >> 6, kg = u & 63;
            uint32_t d = n * 1024 + ((kg * 16) ^ ((n & 7) << 4));
            *(uint4 *)(p + SO_UH + d) =
                *(const uint4 *)(g_Ut_hi + (size_t)(ntile * 64 + n) * 512 + kg * 8);
            *(uint4 *)(p + SO_UL + d) =
                *(const uint4 *)(g_Ut_lo + (size_t)(ntile * 64 + n) * 512 + kg * 8);
        }
    }
    __syncthreads();

    // ---- per-thread cell states (4 cells: [p][mh]) ----
    float cs[2][2], hs[2][2];
#pragma unroll
    for (int p = 0; p < 2; ++p) {
        int nb = (lane & 1) ? 2 + p : p;
        int hg = hbash + nb * 2;
#pragma unroll
        for (int mh = 0; mh < 2; ++mh) {
            int mg = mg0 + mh * 8;
            cs[p][mh] = __ldg(c0in + (size_t)mg * 512 + hg);
            hs[p][mh] = __ldg(h0in + (size_t)mg * 512 + hg);
        }
    }

    // ---- time loop with fast monotone-counter barrier ----
    for (int t = 0; t < TT; ++t) {
#pragma unroll
        for (int a = 0; a < 4; ++a)
#pragma unroll
            for (int r = 0; r < 4; ++r) C[a][r] = 0.0f;
        run_gemm<4, 1024>(g_ahi[t & 1], g_alo[t & 1], HH, m0, smb, tid, lane, wm, wn, C);

        const int bs = __ldg(bsz + t);

        // gate sums = C + pre; exchange complementary gate pairs with lane^1
        float own[2][4], R[2][4];
#pragma unroll
        for (int p = 0; p < 2; ++p)
#pragma unroll
            for (int r = 0; r < 4; ++r) {
                float lo2 = C[p][r] + pre[p][r];
                float hi2 = C[2 + p][r] + pre[2 + p][r];
                own[p][r] = (lane & 1) ? hi2 : lo2;
                float send = (lane & 1) ? lo2 : hi2;
                R[p][r] = __shfl_xor_sync(0xffffffffu, send, 1);
            }

#pragma unroll
        for (int p = 0; p < 2; ++p) {
            int nb = (lane & 1) ? 2 + p : p;
            int hg = hbash + nb * 2;
#pragma unroll
            for (int mh = 0; mh < 2; ++mh) {
                float vi, vf, vg, vo;
                if (lane & 1) {
                    vg = own[p][mh * 2]; vo = own[p][mh * 2 + 1];
                    vi = R[p][mh * 2];   vf = R[p][mh * 2 + 1];
                } else {
                    vi = own[p][mh * 2]; vf = own[p][mh * 2 + 1];
                    vg = R[p][mh * 2];   vo = R[p][mh * 2 + 1];
                }
                int mg = mg0 + mh * 8;
                float cn = sigf(vf) * cs[p][mh] + sigf(vi) * tanhfast(vg);
                float hn = sigf(vo) * tanhfast(cn);
                bool act = (mg < bs);
                float o = act ? hn : 0.0f;
                if (act) { cs[p][mh] = cn; hs[p][mh] = hn; }
                out[(size_t)t * BH + (size_t)mg * 512 + hg] = o;
            }
        }

        if (t < TT - 1) {
            // drift on h dims 0,1 (ntile 0, wn 0, nb 0 → even lanes, cc 0 and 2)
            if (ntile == 0 && wn == 0) {
#pragma unroll
                for (int mh = 0; mh < 2; ++mh) {
                    float mine = hs[0][mh];
                    float oth = __shfl_xor_sync(0xffffffffu, mine, 2);
                    if (!(lane & 1)) {
                        if (cc == 0)
                            hs[0][mh] = mine + tauv * (1.5f * mine + oth * (1.0f / 1.5f));
                        else if (cc == 2)
                            hs[0][mh] = mine - tauv * (1.5f * oth);
                    }
                }
            }
            __nv_bfloat16 *dh = g_ahi[(t + 1) & 1];
            __nv_bfloat16 *dl = g_alo[(t + 1) & 1];
#pragma unroll
            for (int p = 0; p < 2; ++p) {
                int nb = (lane & 1) ? 2 + p : p;
                int hg = hbash + nb * 2;
#pragma unroll
                for (int mh = 0; mh < 2; ++mh) {
                    int mg = mg0 + mh * 8;
                    float v = hs[p][mh];
                    __nv_bfloat16 bh16 = __float2bfloat16_rn(v);
                    dh[(size_t)mg * 512 + hg] = bh16;
                    dl[(size_t)mg * 512 + hg] =
                        __float2bfloat16_rn(v - __bfloat162float(bh16));
                }
            }
            // grid barrier: release writes, arrive, spin (one thread, no nanosleep)
            __threadfence();
            __syncthreads();
            if (tid == 0) {
                atomicAdd(&g_arr, 1u);
                const unsigned tgt = (unsigned)(t + 1) * NCTA;
                while (ldacq(&g_arr) < tgt) {}
            }
            __syncthreads();
            __threadfence();
        }
    }

    // ---- final h, c ----
    const size_t ofs = (size_t)TT * BH;
#pragma unroll
    for (int p = 0; p < 2; ++p) {
        int nb = (lane & 1) ? 2 + p : p;
        int hg = hbash + nb * 2;
#pragma unroll
        for (int mh = 0; mh < 2; ++mh) {
            int mg = mg0 + mh * 8;
            out[ofs + (size_t)mg * 512 + hg] = hs[p][mh];
            out[ofs + BH + (size_t)mg * 512 + hg] = cs[p][mh];
        }
    }
}

extern "C" void kernel_launch(void *const *d_in, const int *in_sizes, int n_in,
                              void *d_out, int out_size)
{
    const float *rnn = (const float *)d_in[0];
    const int *bsz = (const int *)d_in[1];
    const float *h0 = (const float *)d_in[2];
    const float *c0 = (const float *)d_in[3];
    const float *tau = (const float *)d_in[4];
    const float *Ww = (const float *)d_in[5];
    const float *Wb = (const float *)d_in[6];
    const float *Uw = (const float *)d_in[7];
    float *out = (float *)d_out;

    cudaFuncSetAttribute(lstm_mma, cudaFuncAttributeMaxDynamicSharedMemorySize,
                         SMEM_TOT);
    prep_kernel<<<512, 256>>>(rnn, h0, Ww, Uw);
    lstm_mma<<<NCTA, NTHR, SMEM_TOT>>>(bsz, h0, c0, tau, Wb, out);
}

// round 8
// speedup vs baseline: 1.7490x; 1.1554x over previous
#include <cuda_runtime.h>
#include <cuda_fp16.h>
#include <stdint.h>

#define BB 256
#define TT 512
#define HH 512
#define II 256
#define BH 131072
#define NCTA 128
#define NTHR 256

// SMEM: A dbl-buf 2 x (16K hi + 16K lo) = 64K, then U (single fp16) 64K
#define SO_AL 16384
#define AB1   32768
#define SO_U  65536
#define SMEM_TOT 131072

// ---------------- device globals ----------------
__device__ __align__(16) __half g_Uf[2048 * 512];   // permuted U, fp16
__device__ __align__(16) __half g_Wf[2048 * 256];   // permuted W, fp16
__device__ __align__(16) __half g_x0h[256 * 256];
__device__ __align__(16) __half g_x0l[256 * 256];
__device__ __align__(16) __half g_ah[2][BH];        // h stream hi
__device__ __align__(16) __half g_al[2][BH];        // h stream lo
__device__ unsigned int g_arr;                      // monotone arrival counter

// ---------------- helpers ----------------
__device__ __forceinline__ uint32_t smem_u32(const void *p) {
    uint32_t a;
    asm("{ .reg .u64 t; cvta.to.shared.u64 t, %1; cvt.u32.u64 %0, t; }"
        : "=r"(a) : "l"(p));
    return a;
}
__device__ __forceinline__ void cpa16(uint32_t dst, const void *src) {
    asm volatile("cp.async.cg.shared.global [%0], [%1], 16;"
                 :: "r"(dst), "l"(__cvta_generic_to_global(src)) : "memory");
}
#define CP_COMMIT asm volatile("cp.async.commit_group;" ::: "memory")

__device__ __forceinline__ unsigned ldacq(const unsigned *p) {
    unsigned v;
    asm volatile("ld.acquire.gpu.global.u32 %0, [%1];"
                 : "=r"(v) : "l"(__cvta_generic_to_global((void *)p)) : "memory");
    return v;
}
__device__ __forceinline__ void ldsm4(uint32_t addr, uint32_t r[4]) {
    asm volatile("ldmatrix.sync.aligned.m8n8.x4.shared.b16 {%0,%1,%2,%3}, [%4];"
                 : "=r"(r[0]), "=r"(r[1]), "=r"(r[2]), "=r"(r[3]) : "r"(addr));
}
__device__ __forceinline__ void mmaf16(float c[4], const uint32_t a[4],
                                       uint32_t b0, uint32_t b1) {
    asm volatile(
        "mma.sync.aligned.m16n8k16.row.col.f32.f16.f16.f32 "
        "{%0,%1,%2,%3}, {%4,%5,%6,%7}, {%8,%9}, {%0,%1,%2,%3};"
        : "+f"(c[0]), "+f"(c[1]), "+f"(c[2]), "+f"(c[3])
        : "r"(a[0]), "r"(a[1]), "r"(a[2]), "r"(a[3]), "r"(b0), "r"(b1));
}
__device__ __forceinline__ float sigf(float x) {
    return __fdividef(1.0f, 1.0f + __expf(-x));
}
__device__ __forceinline__ float tanhfast(float x) {
    return 1.0f - __fdividef(2.0f, __expf(2.0f * x) + 1.0f);
}

// ---------------- prep: permute cols (gate-interleave) + fp16 convert/split ----------
__global__ void prep_kernel(const float *__restrict__ rnn,
                            const float *__restrict__ h0,
                            const float *__restrict__ Ww,
                            const float *__restrict__ Uw)
{
    if (blockIdx.x == 0 && threadIdx.x == 0) g_arr = 0u;
    const long TU = 512L * 2048, TW = 256L * 2048, TX = 256L * 256, TH = 256L * 512;
    const long TOT = TU + TW + TX + TH;
    for (long i = (long)blockIdx.x * blockDim.x + threadIdx.x; i < TOT;
         i += (long)gridDim.x * blockDim.x) {
        if (i < TU) {
            long k = i >> 11;
            int n = (int)(i & 2047);
            int p = ((n & 511) << 2) | (n >> 9);   // h*4 + gate
            g_Uf[(long)p * 512 + k] = __float2half_rn(Uw[i]);
        } else if (i < TU + TW) {
            long j = i - TU;
            long k = j >> 11;
            int n = (int)(j & 2047);
            int p = ((n & 511) << 2) | (n >> 9);
            g_Wf[(long)p * 256 + k] = __float2half_rn(Ww[j]);
        } else if (i < TU + TW + TX) {
            long j = i - TU - TW;
            float v = rnn[j];
            __half hi = __float2half_rn(v);
            g_x0h[j] = hi;
            g_x0l[j] = __float2half_rn(v - __half2float(hi));
        } else {
            long j = i - TU - TW - TX;
            float v = h0[j];
            __half hi = __float2half_rn(v);
            g_ah[0][j] = hi;
            g_al[0][j] = __float2half_rn(v - __half2float(hi));
        }
    }
}

// ---------------- GEMM: C[64x64] += A[64 x NC*128] * B(smem)^T ----
// 2-pass: A split fp16 (hi+lo), B single fp16. KC = 128.
// A buf: 64 rows x 256B pitch; hi at buf base, lo at +SO_AL; buffers at 0 / AB1.
template <int NC, int BPITCH>
__device__ __forceinline__ void run_gemm(
    const __half *__restrict__ gh, const __half *__restrict__ gl,
    int ldk, int m0, uint32_t smb, int tid, int lane, int wm, int wn, float C[4][4])
{
    __syncthreads();   // A-buffer reuse guard across calls
    {
#pragma unroll
        for (int i = 0; i < 4; ++i) {
            int u = tid + 256 * i, m = u >> 4, kg = u & 15;
            size_t go = (size_t)(m0 + m) * ldk + kg * 8;
            uint32_t d = (uint32_t)(m * 256 + ((kg * 16) ^ ((m & 7) << 4)));
            cpa16(smb + d, gh + go);
            cpa16(smb + d + SO_AL, gl + go);
        }
        CP_COMMIT;
    }
    for (int kc = 0; kc < NC; ++kc) {
        if (kc + 1 < NC) {
            __syncthreads();
#pragma unroll
            for (int i = 0; i < 4; ++i) {
                int u = tid + 256 * i, m = u >> 4, kg = u & 15;
                size_t go = (size_t)(m0 + m) * ldk + (kc + 1) * 128 + kg * 8;
                uint32_t d = (uint32_t)(((kc + 1) & 1) * AB1 + m * 256 +
                                        ((kg * 16) ^ ((m & 7) << 4)));
                cpa16(smb + d, gh + go);
                cpa16(smb + d + SO_AL, gl + go);
            }
            CP_COMMIT;
            asm volatile("cp.async.wait_group 1;" ::: "memory");
        } else {
            asm volatile("cp.async.wait_group 0;" ::: "memory");
        }
        __syncthreads();
        uint32_t ab = smb + (kc & 1) * AB1;
#pragma unroll
        for (int sub = 0; sub < 8; ++sub) {
            uint32_t ahr[4], alr[4];
            {
                int mat = lane >> 3, rr = lane & 7;
                int mloc = wm * 16 + ((mat & 1) << 3) + rr;
                int kb = sub * 32 + ((mat >> 1) << 4);
                uint32_t off = mloc * 256 + (kb ^ ((mloc & 7) << 4));
                ldsm4(ab + off, ahr);
                ldsm4(ab + SO_AL + off, alr);
            }
            uint32_t bf[8];
            const int kg2 = (kc * 128 + sub * 16) * 2;
#pragma unroll
            for (int half = 0; half < 2; ++half) {
                int mat = lane >> 3, rr = lane & 7;
                int nloc = wn * 32 + half * 16 + ((mat >> 1) << 3) + rr;
                int kb = kg2 + ((mat & 1) << 4);
                uint32_t off = nloc * BPITCH + (kb ^ ((nloc & 7) << 4));
                ldsm4(smb + SO_U + off, &bf[half * 4]);
            }
#pragma unroll
            for (int nb = 0; nb < 4; ++nb) {
                mmaf16(C[nb], ahr, bf[nb * 2], bf[nb * 2 + 1]);
                mmaf16(C[nb], alr, bf[nb * 2], bf[nb * 2 + 1]);
            }
        }
    }
}

// ---------------- main persistent kernel ----------------
__global__ void __launch_bounds__(NTHR, 1) lstm_mma(
    const int *__restrict__ bsz, const float *__restrict__ h0in,
    const float *__restrict__ c0in, const float *__restrict__ taup,
    const float *__restrict__ Wb, float *__restrict__ out)
{
    extern __shared__ char sm[];
    const uint32_t smb = smem_u32(sm);
    const int tid = threadIdx.x, cta = blockIdx.x;
    const int lane = tid & 31, wid = tid >> 5;
    const int wm = wid & 3, wn = wid >> 2;
    const int mtile = cta & 3, ntile = cta >> 2;
    const int m0 = mtile * 64;
    const float tauv = __ldg(taup);

    const int cc = lane & 3;
    const int hbash = ntile * 16 + wn * 8 + (cc >> 1);
    const int mg0 = m0 + wm * 16 + (lane >> 2);

    // ---- fill W into U slot (pitch 512B), compute pre via MMA ----
    {
        char *p = sm;
#pragma unroll
        for (int i = 0; i < 8; ++i) {
            int u = tid + 256 * i, n = u >> 5, kg = u & 31;
            uint32_t d = n * 512 + ((kg * 16) ^ ((n & 7) << 4));
            *(uint4 *)(p + SO_U + d) =
                *(const uint4 *)(g_Wf + (size_t)(ntile * 64 + n) * 256 + kg * 8);
        }
    }
    __syncthreads();

    float C[4][4];
#pragma unroll
    for (int a = 0; a < 4; ++a)
#pragma unroll
        for (int r = 0; r < 4; ++r) C[a][r] = 0.0f;
    run_gemm<2, 512>(g_x0h, g_x0l, II, m0, smb, tid, lane, wm, wn, C);

    float pre[4][4];
#pragma unroll
    for (int nb = 0; nb < 4; ++nb)
#pragma unroll
        for (int r = 0; r < 4; ++r) {
            int gate = (cc * 2 + (r & 1)) & 3;
            int hg = ntile * 16 + wn * 8 + nb * 2 + (cc >> 1);
            pre[nb][r] = C[nb][r] + __ldg(Wb + gate * 512 + hg);
        }
    __syncthreads();

    // ---- fill U resident (pitch 1024B, fp16) ----
    {
        char *p = sm;
#pragma unroll
        for (int i = 0; i < 16; ++i) {
            int u = tid + 256 * i, n = u >> 6, kg = u & 63;
            uint32_t d = n * 1024 + ((kg * 16) ^ ((n & 7) << 4));
            *(uint4 *)(p + SO_U + d) =
                *(const uint4 *)(g_Uf + (size_t)(ntile * 64 + n) * 512 + kg * 8);
        }
    }
    __syncthreads();

    // ---- per-thread cell states (4 cells: [p][mh]) ----
    float cs[2][2], hs[2][2];
#pragma unroll
    for (int p = 0; p < 2; ++p) {
        int nb = (lane & 1) ? 2 + p : p;
        int hg = hbash + nb * 2;
#pragma unroll
        for (int mh = 0; mh < 2; ++mh) {
            int mg = mg0 + mh * 8;
            cs[p][mh] = __ldg(c0in + (size_t)mg * 512 + hg);
            hs[p][mh] = __ldg(h0in + (size_t)mg * 512 + hg);
        }
    }

    // ---- time loop with monotone-counter barrier ----
    for (int t = 0; t < TT; ++t) {
#pragma unroll
        for (int a = 0; a < 4; ++a)
#pragma unroll
            for (int r = 0; r < 4; ++r) C[a][r] = 0.0f;
        run_gemm<4, 1024>(g_ah[t & 1], g_al[t & 1], HH, m0, smb, tid, lane, wm, wn, C);

        const int bs = __ldg(bsz + t);

        // gate sums = C + pre; exchange complementary gate pairs with lane^1
        float own[2][4], R[2][4];
#pragma unroll
        for (int p = 0; p < 2; ++p)
#pragma unroll
            for (int r = 0; r < 4; ++r) {
                float lo2 = C[p][r] + pre[p][r];
                float hi2 = C[2 + p][r] + pre[2 + p][r];
                own[p][r] = (lane & 1) ? hi2 : lo2;
                float send = (lane & 1) ? lo2 : hi2;
                R[p][r] = __shfl_xor_sync(0xffffffffu, send, 1);
            }

#pragma unroll
        for (int p = 0; p < 2; ++p) {
            int nb = (lane & 1) ? 2 + p : p;
            int hg = hbash + nb * 2;
#pragma unroll
            for (int mh = 0; mh < 2; ++mh) {
                float vi, vf, vg, vo;
                if (lane & 1) {
                    vg = own[p][mh * 2]; vo = own[p][mh * 2 + 1];
                    vi = R[p][mh * 2];   vf = R[p][mh * 2 + 1];
                } else {
                    vi = own[p][mh * 2]; vf = own[p][mh * 2 + 1];
                    vg = R[p][mh * 2];   vo = R[p][mh * 2 + 1];
                }
                int mg = mg0 + mh * 8;
                float cn = sigf(vf) * cs[p][mh] + sigf(vi) * tanhfast(vg);
                float hn = sigf(vo) * tanhfast(cn);
                bool act = (mg < bs);
                float o = act ? hn : 0.0f;
                if (act) { cs[p][mh] = cn; hs[p][mh] = hn; }
                out[(size_t)t * BH + (size_t)mg * 512 + hg] = o;
            }
        }

        if (t < TT - 1) {
            // drift on h dims 0,1 (ntile 0, wn 0, nb 0 → even lanes, cc 0 and 2)
            if (ntile == 0 && wn == 0) {
#pragma unroll
                for (int mh = 0; mh < 2; ++mh) {
                    float mine = hs[0][mh];
                    float oth = __shfl_xor_sync(0xffffffffu, mine, 2);
                    if (!(lane & 1)) {
                        if (cc == 0)
                            hs[0][mh] = mine + tauv * (1.5f * mine + oth * (1.0f / 1.5f));
                        else if (cc == 2)
                            hs[0][mh] = mine - tauv * (1.5f * oth);
                    }
                }
            }
            __half *dh = g_ah[(t + 1) & 1];
            __half *dl = g_al[(t + 1) & 1];
#pragma unroll
            for (int p = 0; p < 2; ++p) {
                int nb = (lane & 1) ? 2 + p : p;
                int hg = hbash + nb * 2;
#pragma unroll
                for (int mh = 0; mh < 2; ++mh) {
                    int mg = mg0 + mh * 8;
                    float v = hs[p][mh];
                    __half h16 = __float2half_rn(v);
                    dh[(size_t)mg * 512 + hg] = h16;
                    dl[(size_t)mg * 512 + hg] =
                        __float2half_rn(v - __half2float(h16));
                }
            }
            // grid barrier: release writes, arrive, spin (one thread)
            __threadfence();
            __syncthreads();
            if (tid == 0) {
                atomicAdd(&g_arr, 1u);
                const unsigned tgt = (unsigned)(t + 1) * NCTA;
                while (ldacq(&g_arr) < tgt) {}
            }
            __syncthreads();
            __threadfence();
        }
    }

    // ---- final h, c ----
    const size_t ofs = (size_t)TT * BH;
#pragma unroll
    for (int p = 0; p < 2; ++p) {
        int nb = (lane & 1) ? 2 + p : p;
        int hg = hbash + nb * 2;
#pragma unroll
        for (int mh = 0; mh < 2; ++mh) {
            int mg = mg0 + mh * 8;
            out[ofs + (size_t)mg * 512 + hg] = hs[p][mh];
            out[ofs + BH + (size_t)mg * 512 + hg] = cs[p][mh];
        }
    }
}

extern "C" void kernel_launch(void *const *d_in, const int *in_sizes, int n_in,
                              void *d_out, int out_size)
{
    const float *rnn = (const float *)d_in[0];
    const int *bsz = (const int *)d_in[1];
    const float *h0 = (const float *)d_in[2];
    const float *c0 = (const float *)d_in[3];
    const float *tau = (const float *)d_in[4];
    const float *Ww = (const float *)d_in[5];
    const float *Wb = (const float *)d_in[6];
    const float *Uw = (const float *)d_in[7];
    float *out = (float *)d_out;

    cudaFuncSetAttribute(lstm_mma, cudaFuncAttributeMaxDynamicSharedMemorySize,
                         SMEM_TOT);
    prep_kernel<<<512, 256>>>(rnn, h0, Ww, Uw);
    lstm_mma<<<NCTA, NTHR, SMEM_TOT>>>(bsz, h0, c0, tau, Wb, out);
}

// round 9
// speedup vs baseline: 2.0478x; 1.1708x over previous
#include <cuda_runtime.h>
#include <cuda_fp16.h>
#include <stdint.h>

#define BB 256
#define TT 512
#define HH 512
#define II 256
#define BH 131072
#define NCTA 128
#define NTHR 256

// SMEM: A dbl-buf 2 x (32K hi + 32K lo) = 128K, then U (fp16) 64K
#define SO_AL 32768
#define AB1   65536
#define SO_U  131072
#define SMEM_TOT 196608

// ---------------- device globals ----------------
__device__ __align__(16) __half g_Uf[2048 * 512];   // permuted U, fp16
__device__ __align__(16) __half g_Wf[2048 * 256];   // permuted W, fp16
__device__ __align__(16) __half g_x0h[256 * 256];
__device__ __align__(16) __half g_x0l[256 * 256];
__device__ __align__(16) __half g_ah[2][BH];        // h stream hi
__device__ __align__(16) __half g_al[2][BH];        // h stream lo
__device__ unsigned int g_arrm[4 * 32];             // per-mtile counters, 128B apart

// ---------------- helpers ----------------
__device__ __forceinline__ uint32_t smem_u32(const void *p) {
    uint32_t a;
    asm("{ .reg .u64 t; cvta.to.shared.u64 t, %1; cvt.u32.u64 %0, t; }"
        : "=r"(a) : "l"(p));
    return a;
}
__device__ __forceinline__ void cpa16(uint32_t dst, const void *src) {
    asm volatile("cp.async.cg.shared.global [%0], [%1], 16;"
                 :: "r"(dst), "l"(__cvta_generic_to_global(src)) : "memory");
}
#define CP_COMMIT asm volatile("cp.async.commit_group;" ::: "memory")

__device__ __forceinline__ unsigned ldacq(const unsigned *p) {
    unsigned v;
    asm volatile("ld.acquire.gpu.global.u32 %0, [%1];"
                 : "=r"(v) : "l"(__cvta_generic_to_global((void *)p)) : "memory");
    return v;
}
__device__ __forceinline__ void ldsm4(uint32_t addr, uint32_t r[4]) {
    asm volatile("ldmatrix.sync.aligned.m8n8.x4.shared.b16 {%0,%1,%2,%3}, [%4];"
                 : "=r"(r[0]), "=r"(r[1]), "=r"(r[2]), "=r"(r[3]) : "r"(addr));
}
__device__ __forceinline__ void mmaf16(float c[4], const uint32_t a[4],
                                       uint32_t b0, uint32_t b1) {
    asm volatile(
        "mma.sync.aligned.m16n8k16.row.col.f32.f16.f16.f32 "
        "{%0,%1,%2,%3}, {%4,%5,%6,%7}, {%8,%9}, {%0,%1,%2,%3};"
        : "+f"(c[0]), "+f"(c[1]), "+f"(c[2]), "+f"(c[3])
        : "r"(a[0]), "r"(a[1]), "r"(a[2]), "r"(a[3]), "r"(b0), "r"(b1));
}
__device__ __forceinline__ float sigf(float x) {
    return __fdividef(1.0f, 1.0f + __expf(-x));
}
__device__ __forceinline__ float tanhfast(float x) {
    return 1.0f - __fdividef(2.0f, __expf(2.0f * x) + 1.0f);
}

// ---------------- prep: permute cols (gate-interleave) + fp16 convert/split ----------
__global__ void prep_kernel(const float *__restrict__ rnn,
                            const float *__restrict__ h0,
                            const float *__restrict__ Ww,
                            const float *__restrict__ Uw)
{
    if (blockIdx.x == 0 && threadIdx.x < 128)
        g_arrm[threadIdx.x] = 0u;
    const long TU = 512L * 2048, TW = 256L * 2048, TX = 256L * 256, TH = 256L * 512;
    const long TOT = TU + TW + TX + TH;
    for (long i = (long)blockIdx.x * blockDim.x + threadIdx.x; i < TOT;
         i += (long)gridDim.x * blockDim.x) {
        if (i < TU) {
            long k = i >> 11;
            int n = (int)(i & 2047);
            int p = ((n & 511) << 2) | (n >> 9);   // h*4 + gate
            g_Uf[(long)p * 512 + k] = __float2half_rn(Uw[i]);
        } else if (i < TU + TW) {
            long j = i - TU;
            long k = j >> 11;
            int n = (int)(j & 2047);
            int p = ((n & 511) << 2) | (n >> 9);
            g_Wf[(long)p * 256 + k] = __float2half_rn(Ww[j]);
        } else if (i < TU + TW + TX) {
            long j = i - TU - TW;
            float v = rnn[j];
            __half hi = __float2half_rn(v);
            g_x0h[j] = hi;
            g_x0l[j] = __float2half_rn(v - __half2float(hi));
        } else {
            long j = i - TU - TW - TX;
            float v = h0[j];
            __half hi = __float2half_rn(v);
            g_ah[0][j] = hi;
            g_al[0][j] = __float2half_rn(v - __half2float(hi));
        }
    }
}

// ---------------- GEMM: C[64x64] += A[64 x NC*256] * B(smem)^T ----
// 2-pass: A split fp16 (hi+lo), B single fp16. KC = 256; NC chunks (1 or 2).
// A buf: 64 rows x 512B pitch; hi at buf base, lo at +SO_AL; buffers at 0 / AB1.
template <int NC, int BPITCH>
__device__ __forceinline__ void run_gemm(
    const __half *__restrict__ gh, const __half *__restrict__ gl,
    int ldk, int m0, uint32_t smb, int tid, int lane, int wm, int wn, float C[4][4])
{
    __syncthreads();   // buffer reuse guard vs previous use
#pragma unroll
    for (int c = 0; c < NC; ++c) {
#pragma unroll
        for (int i = 0; i < 8; ++i) {
            int u = tid + 256 * i, m = u >> 5, kg = u & 31;
            size_t go = (size_t)(m0 + m) * ldk + c * 256 + kg * 8;
            uint32_t d = (uint32_t)(c * AB1 + m * 512 + ((kg * 16) ^ ((m & 7) << 4)));
            cpa16(smb + d, gh + go);
            cpa16(smb + d + SO_AL, gl + go);
        }
        CP_COMMIT;
    }
#pragma unroll
    for (int kc = 0; kc < NC; ++kc) {
        if (NC == 2 && kc == 0) {
            asm volatile("cp.async.wait_group 1;" ::: "memory");
        } else {
            asm volatile("cp.async.wait_group 0;" ::: "memory");
        }
        __syncthreads();
        uint32_t ab = smb + kc * AB1;
#pragma unroll
        for (int sub = 0; sub < 16; ++sub) {
            uint32_t ahr[4], alr[4];
            {
                int mat = lane >> 3, rr = lane & 7;
                int mloc = wm * 16 + ((mat & 1) << 3) + rr;
                int kb = sub * 32 + ((mat >> 1) << 4);
                uint32_t off = mloc * 512 + (kb ^ ((mloc & 7) << 4));
                ldsm4(ab + off, ahr);
                ldsm4(ab + SO_AL + off, alr);
            }
            uint32_t bf[8];
            const int kg2 = (kc * 256 + sub * 16) * 2;
#pragma unroll
            for (int half = 0; half < 2; ++half) {
                int mat = lane >> 3, rr = lane & 7;
                int nloc = wn * 32 + half * 16 + ((mat >> 1) << 3) + rr;
                int kb = kg2 + ((mat & 1) << 4);
                uint32_t off = nloc * BPITCH + (kb ^ ((nloc & 7) << 4));
                ldsm4(smb + SO_U + off, &bf[half * 4]);
            }
#pragma unroll
            for (int nb = 0; nb < 4; ++nb) {
                mmaf16(C[nb], ahr, bf[nb * 2], bf[nb * 2 + 1]);
                mmaf16(C[nb], alr, bf[nb * 2], bf[nb * 2 + 1]);
            }
        }
    }
}

// ---------------- main persistent kernel ----------------
__global__ void __launch_bounds__(NTHR, 1) lstm_mma(
    const int *__restrict__ bsz, const float *__restrict__ h0in,
    const float *__restrict__ c0in, const float *__restrict__ taup,
    const float *__restrict__ Wb, float *__restrict__ out)
{
    extern __shared__ char sm[];
    const uint32_t smb = smem_u32(sm);
    const int tid = threadIdx.x, cta = blockIdx.x;
    const int lane = tid & 31, wid = tid >> 5;
    const int wm = wid & 3, wn = wid >> 2;
    const int mtile = cta & 3, ntile = cta >> 2;
    const int m0 = mtile * 64;
    const float tauv = __ldg(taup);
    unsigned *mybar = &g_arrm[mtile * 32];

    const int cc = lane & 3;
    const int hbash = ntile * 16 + wn * 8 + (cc >> 1);
    const int mg0 = m0 + wm * 16 + (lane >> 2);

    // ---- fill W into U slot (pitch 512B), compute pre via MMA ----
    {
        char *p = sm;
#pragma unroll
        for (int i = 0; i < 8; ++i) {
            int u = tid + 256 * i, n = u >> 5, kg = u & 31;
            uint32_t d = n * 512 + ((kg * 16) ^ ((n & 7) << 4));
            *(uint4 *)(p + SO_U + d) =
                *(const uint4 *)(g_Wf + (size_t)(ntile * 64 + n) * 256 + kg * 8);
        }
    }
    __syncthreads();

    float C[4][4];
#pragma unroll
    for (int a = 0; a < 4; ++a)
#pragma unroll
        for (int r = 0; r < 4; ++r) C[a][r] = 0.0f;
    run_gemm<1, 512>(g_x0h, g_x0l, II, m0, smb, tid, lane, wm, wn, C);

    float pre[4][4];
#pragma unroll
    for (int nb = 0; nb < 4; ++nb)
#pragma unroll
        for (int r = 0; r < 4; ++r) {
            int gate = (cc * 2 + (r & 1)) & 3;
            int hg = ntile * 16 + wn * 8 + nb * 2 + (cc >> 1);
            pre[nb][r] = C[nb][r] + __ldg(Wb + gate * 512 + hg);
        }
    __syncthreads();

    // ---- fill U resident (pitch 1024B, fp16) ----
    {
        char *p = sm;
#pragma unroll
        for (int i = 0; i < 16; ++i) {
            int u = tid + 256 * i, n = u >> 6, kg = u & 63;
            uint32_t d = n * 1024 + ((kg * 16) ^ ((n & 7) << 4));
            *(uint4 *)(p + SO_U + d) =
                *(const uint4 *)(g_Uf + (size_t)(ntile * 64 + n) * 512 + kg * 8);
        }
    }
    __syncthreads();

    // ---- per-thread cell states (4 cells: [p][mh]) ----
    float cs[2][2], hs[2][2];
#pragma unroll
    for (int p = 0; p < 2; ++p) {
        int nb = (lane & 1) ? 2 + p : p;
        int hg = hbash + nb * 2;
#pragma unroll
        for (int mh = 0; mh < 2; ++mh) {
            int mg = mg0 + mh * 8;
            cs[p][mh] = __ldg(c0in + (size_t)mg * 512 + hg);
            hs[p][mh] = __ldg(h0in + (size_t)mg * 512 + hg);
        }
    }

    // ---- time loop: per-mtile barrier groups (32 CTAs each, fully decoupled) ----
    for (int t = 0; t < TT; ++t) {
#pragma unroll
        for (int a = 0; a < 4; ++a)
#pragma unroll
            for (int r = 0; r < 4; ++r) C[a][r] = 0.0f;
        run_gemm<2, 1024>(g_ah[t & 1], g_al[t & 1], HH, m0, smb, tid, lane, wm, wn, C);

        const int bs = __ldg(bsz + t);

        // gate sums = C + pre; exchange complementary gate pairs with lane^1
        float own[2][4], R[2][4];
#pragma unroll
        for (int p = 0; p < 2; ++p)
#pragma unroll
            for (int r = 0; r < 4; ++r) {
                float lo2 = C[p][r] + pre[p][r];
                float hi2 = C[2 + p][r] + pre[2 + p][r];
                own[p][r] = (lane & 1) ? hi2 : lo2;
                float send = (lane & 1) ? lo2 : hi2;
                R[p][r] = __shfl_xor_sync(0xffffffffu, send, 1);
            }

#pragma unroll
        for (int p = 0; p < 2; ++p) {
            int nb = (lane & 1) ? 2 + p : p;
            int hg = hbash + nb * 2;
#pragma unroll
            for (int mh = 0; mh < 2; ++mh) {
                float vi, vf, vg, vo;
                if (lane & 1) {
                    vg = own[p][mh * 2]; vo = own[p][mh * 2 + 1];
                    vi = R[p][mh * 2];   vf = R[p][mh * 2 + 1];
                } else {
                    vi = own[p][mh * 2]; vf = own[p][mh * 2 + 1];
                    vg = R[p][mh * 2];   vo = R[p][mh * 2 + 1];
                }
                int mg = mg0 + mh * 8;
                float cn = sigf(vf) * cs[p][mh] + sigf(vi) * tanhfast(vg);
                float hn = sigf(vo) * tanhfast(cn);
                bool act = (mg < bs);
                float o = act ? hn : 0.0f;
                if (act) { cs[p][mh] = cn; hs[p][mh] = hn; }
                out[(size_t)t * BH + (size_t)mg * 512 + hg] = o;
            }
        }

        if (t < TT - 1) {
            // drift on h dims 0,1 (ntile 0, wn 0, nb 0 → even lanes, cc 0 and 2)
            if (ntile == 0 && wn == 0) {
#pragma unroll
                for (int mh = 0; mh < 2; ++mh) {
                    float mine = hs[0][mh];
                    float oth = __shfl_xor_sync(0xffffffffu, mine, 2);
                    if (!(lane & 1)) {
                        if (cc == 0)
                            hs[0][mh] = mine + tauv * (1.5f * mine + oth * (1.0f / 1.5f));
                        else if (cc == 2)
                            hs[0][mh] = mine - tauv * (1.5f * oth);
                    }
                }
            }
            __half *dh = g_ah[(t + 1) & 1];
            __half *dl = g_al[(t + 1) & 1];
#pragma unroll
            for (int p = 0; p < 2; ++p) {
                int nb = (lane & 1) ? 2 + p : p;
                int hg = hbash + nb * 2;
#pragma unroll
                for (int mh = 0; mh < 2; ++mh) {
                    int mg = mg0 + mh * 8;
                    float v = hs[p][mh];
                    __half h16 = __float2half_rn(v);
                    dh[(size_t)mg * 512 + hg] = h16;
                    dl[(size_t)mg * 512 + hg] =
                        __float2half_rn(v - __half2float(h16));
                }
            }
            // per-mtile barrier: release writes, arrive, spin (one thread)
            __threadfence();
            __syncthreads();
            if (tid == 0) {
                atomicAdd(mybar, 1u);
                const unsigned tgt = (unsigned)(t + 1) * 32u;
                while (ldacq(mybar) < tgt) {}
            }
            __syncthreads();
        }
    }

    // ---- final h, c ----
    const size_t ofs = (size_t)TT * BH;
#pragma unroll
    for (int p = 0; p < 2; ++p) {
        int nb = (lane & 1) ? 2 + p : p;
        int hg = hbash + nb * 2;
#pragma unroll
        for (int mh = 0; mh < 2; ++mh) {
            int mg = mg0 + mh * 8;
            out[ofs + (size_t)mg * 512 + hg] = hs[p][mh];
            out[ofs + BH + (size_t)mg * 512 + hg] = cs[p][mh];
        }
    }
}

extern "C" void kernel_launch(void *const *d_in, const int *in_sizes, int n_in,
                              void *d_out, int out_size)
{
    const float *rnn = (const float *)d_in[0];
    const int *bsz = (const int *)d_in[1];
    const float *h0 = (const float *)d_in[2];
    const float *c0 = (const float *)d_in[3];
    const float *tau = (const float *)d_in[4];
    const float *Wb = (const float *)d_in[6];
    const float *Ww = (const float *)d_in[5];
    const float *Uw = (const float *)d_in[7];
    float *out = (float *)d_out;

    cudaFuncSetAttribute(lstm_mma, cudaFuncAttributeMaxDynamicSharedMemorySize,
                         SMEM_TOT);
    prep_kernel<<<512, 256>>>(rnn, h0, Ww, Uw);
    lstm_mma<<<NCTA, NTHR, SMEM_TOT>>>(bsz, h0, c0, tau, Wb, out);
}

// round 10
// speedup vs baseline: 2.1936x; 1.0712x over previous
#include <cuda_runtime.h>
#include <cuda_fp16.h>
#include <stdint.h>

#define BB 256
#define TT 512
#define HH 512
#define II 256
#define BH 131072
#define NCTA 128
#define NTHR 256

// CTA tile: m32 x n128. 8 mtiles x 16 ntiles.
// SMEM: A dbl-buf 2 x (16K hi + 16K lo) = 64K, then U (fp16, n128 x k512) 128K
#define SO_AL 16384
#define AB1   32768
#define SO_U  65536
#define SMEM_TOT 196608

// ---------------- device globals ----------------
__device__ __align__(16) __half g_Uf[2048 * 512];   // permuted U, fp16
__device__ __align__(16) __half g_Wf[2048 * 256];   // permuted W, fp16
__device__ __align__(16) __half g_x0h[256 * 256];
__device__ __align__(16) __half g_x0l[256 * 256];
__device__ __align__(16) __half g_ah[2][BH];        // h stream hi
__device__ __align__(16) __half g_al[2][BH];        // h stream lo
__device__ unsigned int g_arrm[8 * 32];             // per-mtile counters, 128B apart

// ---------------- helpers ----------------
__device__ __forceinline__ uint32_t smem_u32(const void *p) {
    uint32_t a;
    asm("{ .reg .u64 t; cvta.to.shared.u64 t, %1; cvt.u32.u64 %0, t; }"
        : "=r"(a) : "l"(p));
    return a;
}
__device__ __forceinline__ void cpa16(uint32_t dst, const void *src) {
    asm volatile("cp.async.cg.shared.global [%0], [%1], 16;"
                 :: "r"(dst), "l"(__cvta_generic_to_global(src)) : "memory");
}
#define CP_COMMIT asm volatile("cp.async.commit_group;" ::: "memory")

__device__ __forceinline__ unsigned ldacq(const unsigned *p) {
    unsigned v;
    asm volatile("ld.acquire.gpu.global.u32 %0, [%1];"
                 : "=r"(v) : "l"(__cvta_generic_to_global((void *)p)) : "memory");
    return v;
}
__device__ __forceinline__ void ldsm4(uint32_t addr, uint32_t r[4]) {
    asm volatile("ldmatrix.sync.aligned.m8n8.x4.shared.b16 {%0,%1,%2,%3}, [%4];"
                 : "=r"(r[0]), "=r"(r[1]), "=r"(r[2]), "=r"(r[3]) : "r"(addr));
}
__device__ __forceinline__ void mmaf16(float c[4], const uint32_t a[4],
                                       uint32_t b0, uint32_t b1) {
    asm volatile(
        "mma.sync.aligned.m16n8k16.row.col.f32.f16.f16.f32 "
        "{%0,%1,%2,%3}, {%4,%5,%6,%7}, {%8,%9}, {%0,%1,%2,%3};"
        : "+f"(c[0]), "+f"(c[1]), "+f"(c[2]), "+f"(c[3])
        : "r"(a[0]), "r"(a[1]), "r"(a[2]), "r"(a[3]), "r"(b0), "r"(b1));
}
__device__ __forceinline__ float sigf(float x) {
    return __fdividef(1.0f, 1.0f + __expf(-x));
}
__device__ __forceinline__ float tanhfast(float x) {
    return 1.0f - __fdividef(2.0f, __expf(2.0f * x) + 1.0f);
}

// ---------------- prep: permute cols (gate-interleave) + fp16 convert/split ----------
__global__ void prep_kernel(const float *__restrict__ rnn,
                            const float *__restrict__ h0,
                            const float *__restrict__ Ww,
                            const float *__restrict__ Uw)
{
    if (blockIdx.x == 0 && threadIdx.x < 256)
        g_arrm[threadIdx.x] = 0u;
    const long TU = 512L * 2048, TW = 256L * 2048, TX = 256L * 256, TH = 256L * 512;
    const long TOT = TU + TW + TX + TH;
    for (long i = (long)blockIdx.x * blockDim.x + threadIdx.x; i < TOT;
         i += (long)gridDim.x * blockDim.x) {
        if (i < TU) {
            long k = i >> 11;
            int n = (int)(i & 2047);
            int p = ((n & 511) << 2) | (n >> 9);   // h*4 + gate
            g_Uf[(long)p * 512 + k] = __float2half_rn(Uw[i]);
        } else if (i < TU + TW) {
            long j = i - TU;
            long k = j >> 11;
            int n = (int)(j & 2047);
            int p = ((n & 511) << 2) | (n >> 9);
            g_Wf[(long)p * 256 + k] = __float2half_rn(Ww[j]);
        } else if (i < TU + TW + TX) {
            long j = i - TU - TW;
            float v = rnn[j];
            __half hi = __float2half_rn(v);
            g_x0h[j] = hi;
            g_x0l[j] = __float2half_rn(v - __half2float(hi));
        } else {
            long j = i - TU - TW - TX;
            float v = h0[j];
            __half hi = __float2half_rn(v);
            g_ah[0][j] = hi;
            g_al[0][j] = __float2half_rn(v - __half2float(hi));
        }
    }
}

// ---------------- GEMM: C[32x128] += A[32 x NC*256] * B(smem)^T ----
// 2-pass: A split fp16 (hi+lo), B single fp16. KC=256; NC chunks (1 or 2).
// A buf: 32 rows x 512B pitch; hi at buf base, lo at +SO_AL; buffers 0 / AB1.
// Warp tile m16 x n32 (wm 0..1, wn 0..3).
template <int NC, int BPITCH>
__device__ __forceinline__ void run_gemm(
    const __half *__restrict__ gh, const __half *__restrict__ gl,
    int ldk, int m0, uint32_t smb, int tid, int lane, int wm, int wn, float C[4][4])
{
    __syncthreads();   // buffer reuse guard vs previous use
#pragma unroll
    for (int c = 0; c < NC; ++c) {
#pragma unroll
        for (int i = 0; i < 4; ++i) {
            int u = tid + 256 * i, m = u >> 5, kg = u & 31;
            size_t go = (size_t)(m0 + m) * ldk + c * 256 + kg * 8;
            uint32_t d = (uint32_t)(c * AB1 + m * 512 + ((kg * 16) ^ ((m & 7) << 4)));
            cpa16(smb + d, gh + go);
            cpa16(smb + d + SO_AL, gl + go);
        }
        CP_COMMIT;
    }
#pragma unroll
    for (int kc = 0; kc < NC; ++kc) {
        if (NC == 2 && kc == 0) {
            asm volatile("cp.async.wait_group 1;" ::: "memory");
        } else {
            asm volatile("cp.async.wait_group 0;" ::: "memory");
        }
        __syncthreads();
        uint32_t ab = smb + kc * AB1;
#pragma unroll
        for (int sub = 0; sub < 16; ++sub) {
            uint32_t ahr[4], alr[4];
            {
                int mat = lane >> 3, rr = lane & 7;
                int mloc = wm * 16 + ((mat & 1) << 3) + rr;
                int kb = sub * 32 + ((mat >> 1) << 4);
                uint32_t off = mloc * 512 + (kb ^ ((mloc & 7) << 4));
                ldsm4(ab + off, ahr);
                ldsm4(ab + SO_AL + off, alr);
            }
            uint32_t bf[8];
            const int kg2 = (kc * 256 + sub * 16) * 2;
#pragma unroll
            for (int half = 0; half < 2; ++half) {
                int mat = lane >> 3, rr = lane & 7;
                int nloc = wn * 32 + half * 16 + ((mat >> 1) << 3) + rr;
                int kb = kg2 + ((mat & 1) << 4);
                uint32_t off = nloc * BPITCH + (kb ^ ((nloc & 7) << 4));
                ldsm4(smb + SO_U + off, &bf[half * 4]);
            }
#pragma unroll
            for (int nb = 0; nb < 4; ++nb) {
                mmaf16(C[nb], ahr, bf[nb * 2], bf[nb * 2 + 1]);
                mmaf16(C[nb], alr, bf[nb * 2], bf[nb * 2 + 1]);
            }
        }
    }
}

// ---------------- main persistent kernel ----------------
__global__ void __launch_bounds__(NTHR, 1) lstm_mma(
    const int *__restrict__ bsz, const float *__restrict__ h0in,
    const float *__restrict__ c0in, const float *__restrict__ taup,
    const float *__restrict__ Wb, float *__restrict__ out)
{
    extern __shared__ char sm[];
    const uint32_t smb = smem_u32(sm);
    const int tid = threadIdx.x, cta = blockIdx.x;
    const int lane = tid & 31, wid = tid >> 5;
    const int wm = wid & 1, wn = wid >> 1;           // 2m x 4n warps
    const int mtile = cta & 7, ntile = cta >> 3;     // 8 mtiles x 16 ntiles
    const int m0 = mtile * 32;
    const float tauv = __ldg(taup);
    unsigned *mybar = &g_arrm[mtile * 32];

    const int cc = lane & 3;
    const int hbash = ntile * 32 + wn * 8 + (cc >> 1);
    const int mg0 = m0 + wm * 16 + (lane >> 2);

    // ---- fill W slice (n128 x k256, pitch 512B) into U slot, compute pre ----
    {
        char *p = sm;
#pragma unroll
        for (int i = 0; i < 16; ++i) {
            int u = tid + 256 * i, n = u >> 5, kg = u & 31;
            uint32_t d = n * 512 + ((kg * 16) ^ ((n & 7) << 4));
            *(uint4 *)(p + SO_U + d) =
                *(const uint4 *)(g_Wf + (size_t)(ntile * 128 + n) * 256 + kg * 8);
        }
    }
    __syncthreads();

    float C[4][4];
#pragma unroll
    for (int a = 0; a < 4; ++a)
#pragma unroll
        for (int r = 0; r < 4; ++r) C[a][r] = 0.0f;
    run_gemm<1, 512>(g_x0h, g_x0l, II, m0, smb, tid, lane, wm, wn, C);

    float pre[4][4];
#pragma unroll
    for (int nb = 0; nb < 4; ++nb)
#pragma unroll
        for (int r = 0; r < 4; ++r) {
            int gate = (cc * 2 + (r & 1)) & 3;
            int hg = ntile * 32 + wn * 8 + nb * 2 + (cc >> 1);
            pre[nb][r] = C[nb][r] + __ldg(Wb + gate * 512 + hg);
        }
    __syncthreads();

    // ---- fill U resident (n128 x k512, pitch 1024B, fp16, 128KB) ----
    {
        char *p = sm;
#pragma unroll
        for (int i = 0; i < 32; ++i) {
            int u = tid + 256 * i, n = u >> 6, kg = u & 63;
            uint32_t d = n * 1024 + ((kg * 16) ^ ((n & 7) << 4));
            *(uint4 *)(p + SO_U + d) =
                *(const uint4 *)(g_Uf + (size_t)(ntile * 128 + n) * 512 + kg * 8);
        }
    }
    __syncthreads();

    // ---- per-thread cell states (4 cells: [p][mh]) ----
    float cs[2][2], hs[2][2];
#pragma unroll
    for (int p = 0; p < 2; ++p) {
        int nb = (lane & 1) ? 2 + p : p;
        int hg = hbash + nb * 2;
#pragma unroll
        for (int mh = 0; mh < 2; ++mh) {
            int mg = mg0 + mh * 8;
            cs[p][mh] = __ldg(c0in + (size_t)mg * 512 + hg);
            hs[p][mh] = __ldg(h0in + (size_t)mg * 512 + hg);
        }
    }

    // ---- time loop: per-mtile barrier groups (16 CTAs each) ----
    for (int t = 0; t < TT; ++t) {
#pragma unroll
        for (int a = 0; a < 4; ++a)
#pragma unroll
            for (int r = 0; r < 4; ++r) C[a][r] = 0.0f;
        run_gemm<2, 1024>(g_ah[t & 1], g_al[t & 1], HH, m0, smb, tid, lane, wm, wn, C);

        const int bs = __ldg(bsz + t);

        // gate sums = C + pre; exchange complementary gate pairs with lane^1
        float own[2][4], R[2][4];
#pragma unroll
        for (int p = 0; p < 2; ++p)
#pragma unroll
            for (int r = 0; r < 4; ++r) {
                float lo2 = C[p][r] + pre[p][r];
                float hi2 = C[2 + p][r] + pre[2 + p][r];
                own[p][r] = (lane & 1) ? hi2 : lo2;
                float send = (lane & 1) ? lo2 : hi2;
                R[p][r] = __shfl_xor_sync(0xffffffffu, send, 1);
            }

        float o4[2][2];
#pragma unroll
        for (int p = 0; p < 2; ++p) {
#pragma unroll
            for (int mh = 0; mh < 2; ++mh) {
                float vi, vf, vg, vo;
                if (lane & 1) {
                    vg = own[p][mh * 2]; vo = own[p][mh * 2 + 1];
                    vi = R[p][mh * 2];   vf = R[p][mh * 2 + 1];
                } else {
                    vi = own[p][mh * 2]; vf = own[p][mh * 2 + 1];
                    vg = R[p][mh * 2];   vo = R[p][mh * 2 + 1];
                }
                int mg = mg0 + mh * 8;
                float cn = sigf(vf) * cs[p][mh] + sigf(vi) * tanhfast(vg);
                float hn = sigf(vo) * tanhfast(cn);
                bool act = (mg < bs);
                o4[p][mh] = act ? hn : 0.0f;
                if (act) { cs[p][mh] = cn; hs[p][mh] = hn; }
            }
        }

        if (t < TT - 1) {
            // drift on h dims 0,1 (ntile 0, wn 0, nb 0 → even lanes, cc 0 and 2)
            if (ntile == 0 && wn == 0) {
#pragma unroll
                for (int mh = 0; mh < 2; ++mh) {
                    float mine = hs[0][mh];
                    float oth = __shfl_xor_sync(0xffffffffu, mine, 2);
                    if (!(lane & 1)) {
                        if (cc == 0)
                            hs[0][mh] = mine + tauv * (1.5f * mine + oth * (1.0f / 1.5f));
                        else if (cc == 2)
                            hs[0][mh] = mine - tauv * (1.5f * oth);
                    }
                }
            }
            __half *dh = g_ah[(t + 1) & 1];
            __half *dl = g_al[(t + 1) & 1];
#pragma unroll
            for (int p = 0; p < 2; ++p) {
                int nb = (lane & 1) ? 2 + p : p;
                int hg = hbash + nb * 2;
#pragma unroll
                for (int mh = 0; mh < 2; ++mh) {
                    int mg = mg0 + mh * 8;
                    float v = hs[p][mh];
                    __half h16 = __float2half_rn(v);
                    dh[(size_t)mg * 512 + hg] = h16;
                    dl[(size_t)mg * 512 + hg] =
                        __float2half_rn(v - __half2float(h16));
                }
            }
            // release h writes, arrive; overlap out-stores with barrier wait
            __threadfence();
            __syncthreads();
            if (tid == 0) atomicAdd(mybar, 1u);
#pragma unroll
            for (int p = 0; p < 2; ++p) {
                int nb = (lane & 1) ? 2 + p : p;
                int hg = hbash + nb * 2;
#pragma unroll
                for (int mh = 0; mh < 2; ++mh)
                    out[(size_t)t * BH + (size_t)(mg0 + mh * 8) * 512 + hg] = o4[p][mh];
            }
            if (tid == 0) {
                const unsigned tgt = (unsigned)(t + 1) * 16u;
                while (ldacq(mybar) < tgt) {}
            }
            __syncthreads();
        } else {
#pragma unroll
            for (int p = 0; p < 2; ++p) {
                int nb = (lane & 1) ? 2 + p : p;
                int hg = hbash + nb * 2;
#pragma unroll
                for (int mh = 0; mh < 2; ++mh)
                    out[(size_t)t * BH + (size_t)(mg0 + mh * 8) * 512 + hg] = o4[p][mh];
            }
        }
    }

    // ---- final h, c ----
    const size_t ofs = (size_t)TT * BH;
#pragma unroll
    for (int p = 0; p < 2; ++p) {
        int nb = (lane & 1) ? 2 + p : p;
        int hg = hbash + nb * 2;
#pragma unroll
        for (int mh = 0; mh < 2; ++mh) {
            int mg = mg0 + mh * 8;
            out[ofs + (size_t)mg * 512 + hg] = hs[p][mh];
            out[ofs + BH + (size_t)mg * 512 + hg] = cs[p][mh];
        }
    }
}

extern "C" void kernel_launch(void *const *d_in, const int *in_sizes, int n_in,
                              void *d_out, int out_size)
{
    const float *rnn = (const float *)d_in[0];
    const int *bsz = (const int *)d_in[1];
    const float *h0 = (const float *)d_in[2];
    const float *c0 = (const float *)d_in[3];
    const float *tau = (const float *)d_in[4];
    const float *Ww = (const float *)d_in[5];
    const float *Wb = (const float *)d_in[6];
    const float *Uw = (const float *)d_in[7];
    float *out = (float *)d_out;

    cudaFuncSetAttribute(lstm_mma, cudaFuncAttributeMaxDynamicSharedMemorySize,
                         SMEM_TOT);
    prep_kernel<<<512, 256>>>(rnn, h0, Ww, Uw);
    lstm_mma<<<NCTA, NTHR, SMEM_TOT>>>(bsz, h0, c0, tau, Wb, out);
}

// round 11
// speedup vs baseline: 2.7652x; 1.2606x over previous
#include <cuda_runtime.h>
#include <cuda_fp16.h>
#include <stdint.h>

#define BB 256
#define TT 512
#define HH 512
#define II 256
#define BH 131072
#define NCTA 128
#define NTHR 256

// CTA tile: m32 x n128. 8 mtiles x 16 ntiles.
// SMEM: A hi dbl-buf 2 x 16K = 32K, A lo (pre GEMM only) at 32K..48K,
//       U (fp16, n128 x k512) at 64K..192K
#define AB1   16384
#define SO_AL 32768
#define SO_U  65536
#define SMEM_TOT 196608

// ---------------- device globals ----------------
__device__ __align__(16) __half g_Uf[2048 * 512];   // permuted U, fp16
__device__ __align__(16) __half g_Wf[2048 * 256];   // permuted W, fp16
__device__ __align__(16) __half g_x0h[256 * 256];
__device__ __align__(16) __half g_x0l[256 * 256];
__device__ __align__(16) __half g_ah[2][BH];        // h stream (fp16, 1-pass)
__device__ unsigned int g_arrm[8 * 32];             // per-mtile counters, 128B apart

// ---------------- helpers ----------------
__device__ __forceinline__ uint32_t smem_u32(const void *p) {
    uint32_t a;
    asm("{ .reg .u64 t; cvta.to.shared.u64 t, %1; cvt.u32.u64 %0, t; }"
        : "=r"(a) : "l"(p));
    return a;
}
__device__ __forceinline__ void cpa16(uint32_t dst, const void *src) {
    asm volatile("cp.async.cg.shared.global [%0], [%1], 16;"
                 :: "r"(dst), "l"(__cvta_generic_to_global(src)) : "memory");
}
#define CP_COMMIT asm volatile("cp.async.commit_group;" ::: "memory")

__device__ __forceinline__ unsigned ldacq(const unsigned *p) {
    unsigned v;
    asm volatile("ld.acquire.gpu.global.u32 %0, [%1];"
                 : "=r"(v) : "l"(__cvta_generic_to_global((void *)p)) : "memory");
    return v;
}
__device__ __forceinline__ void ldsm4(uint32_t addr, uint32_t r[4]) {
    asm volatile("ldmatrix.sync.aligned.m8n8.x4.shared.b16 {%0,%1,%2,%3}, [%4];"
                 : "=r"(r[0]), "=r"(r[1]), "=r"(r[2]), "=r"(r[3]) : "r"(addr));
}
__device__ __forceinline__ void mmaf16(float c[4], const uint32_t a[4],
                                       uint32_t b0, uint32_t b1) {
    asm volatile(
        "mma.sync.aligned.m16n8k16.row.col.f32.f16.f16.f32 "
        "{%0,%1,%2,%3}, {%4,%5,%6,%7}, {%8,%9}, {%0,%1,%2,%3};"
        : "+f"(c[0]), "+f"(c[1]), "+f"(c[2]), "+f"(c[3])
        : "r"(a[0]), "r"(a[1]), "r"(a[2]), "r"(a[3]), "r"(b0), "r"(b1));
}
__device__ __forceinline__ float sigf(float x) {
    return __fdividef(1.0f, 1.0f + __expf(-x));
}
__device__ __forceinline__ float tanhfast(float x) {
    return 1.0f - __fdividef(2.0f, __expf(2.0f * x) + 1.0f);
}

// ---------------- prep: permute cols (gate-interleave) + fp16 convert/split ----------
__global__ void prep_kernel(const float *__restrict__ rnn,
                            const float *__restrict__ h0,
                            const float *__restrict__ Ww,
                            const float *__restrict__ Uw)
{
    if (blockIdx.x == 0 && threadIdx.x < 256)
        g_arrm[threadIdx.x] = 0u;
    const long TU = 512L * 2048, TW = 256L * 2048, TX = 256L * 256, TH = 256L * 512;
    const long TOT = TU + TW + TX + TH;
    for (long i = (long)blockIdx.x * blockDim.x + threadIdx.x; i < TOT;
         i += (long)gridDim.x * blockDim.x) {
        if (i < TU) {
            long k = i >> 11;
            int n = (int)(i & 2047);
            int p = ((n & 511) << 2) | (n >> 9);   // h*4 + gate
            g_Uf[(long)p * 512 + k] = __float2half_rn(Uw[i]);
        } else if (i < TU + TW) {
            long j = i - TU;
            long k = j >> 11;
            int n = (int)(j & 2047);
            int p = ((n & 511) << 2) | (n >> 9);
            g_Wf[(long)p * 256 + k] = __float2half_rn(Ww[j]);
        } else if (i < TU + TW + TX) {
            long j = i - TU - TW;
            float v = rnn[j];
            __half hi = __float2half_rn(v);
            g_x0h[j] = hi;
            g_x0l[j] = __float2half_rn(v - __half2float(hi));
        } else {
            long j = i - TU - TW - TX;
            g_ah[0][j] = __float2half_rn(h0[j]);
        }
    }
}

// ---------------- GEMM: C[32x128] += A[32 x NC*256] * B(smem)^T ----
// SPLIT: 2-pass A (hi+lo, pre GEMM). Otherwise 1-pass fp16.
// A buf: 32 rows x 512B pitch; chunk c hi at c*AB1, lo at SO_AL + c*AB1.
// Warp tile m16 x n32 (wm 0..1, wn 0..3).
template <int NC, int BPITCH, bool SPLIT>
__device__ __forceinline__ void run_gemm(
    const __half *__restrict__ gh, const __half *__restrict__ gl,
    int ldk, int m0, uint32_t smb, int tid, int lane, int wm, int wn, float C[4][4])
{
    __syncthreads();   // buffer reuse guard vs previous use
#pragma unroll
    for (int c = 0; c < NC; ++c) {
#pragma unroll
        for (int i = 0; i < 4; ++i) {
            int u = tid + 256 * i, m = u >> 5, kg = u & 31;
            size_t go = (size_t)(m0 + m) * ldk + c * 256 + kg * 8;
            uint32_t d = (uint32_t)(c * AB1 + m * 512 + ((kg * 16) ^ ((m & 7) << 4)));
            cpa16(smb + d, gh + go);
            if (SPLIT) cpa16(smb + d + SO_AL, gl + go);
        }
        CP_COMMIT;
    }
#pragma unroll
    for (int kc = 0; kc < NC; ++kc) {
        if (NC == 2 && kc == 0) {
            asm volatile("cp.async.wait_group 1;" ::: "memory");
        } else {
            asm volatile("cp.async.wait_group 0;" ::: "memory");
        }
        __syncthreads();
        uint32_t ab = smb + kc * AB1;
#pragma unroll
        for (int sub = 0; sub < 16; ++sub) {
            uint32_t ahr[4], alr[4];
            {
                int mat = lane >> 3, rr = lane & 7;
                int mloc = wm * 16 + ((mat & 1) << 3) + rr;
                int kb = sub * 32 + ((mat >> 1) << 4);
                uint32_t off = mloc * 512 + (kb ^ ((mloc & 7) << 4));
                ldsm4(ab + off, ahr);
                if (SPLIT) ldsm4(ab + SO_AL + off, alr);
            }
            uint32_t bf[8];
            const int kg2 = (kc * 256 + sub * 16) * 2;
#pragma unroll
            for (int half = 0; half < 2; ++half) {
                int mat = lane >> 3, rr = lane & 7;
                int nloc = wn * 32 + half * 16 + ((mat >> 1) << 3) + rr;
                int kb = kg2 + ((mat & 1) << 4);
                uint32_t off = nloc * BPITCH + (kb ^ ((nloc & 7) << 4));
                ldsm4(smb + SO_U + off, &bf[half * 4]);
            }
#pragma unroll
            for (int nb = 0; nb < 4; ++nb) {
                mmaf16(C[nb], ahr, bf[nb * 2], bf[nb * 2 + 1]);
                if (SPLIT) mmaf16(C[nb], alr, bf[nb * 2], bf[nb * 2 + 1]);
            }
        }
    }
}

// ---------------- main persistent kernel ----------------
__global__ void __launch_bounds__(NTHR, 1) lstm_mma(
    const int *__restrict__ bsz, const float *__restrict__ h0in,
    const float *__restrict__ c0in, const float *__restrict__ taup,
    const float *__restrict__ Wb, float *__restrict__ out)
{
    extern __shared__ char sm[];
    const uint32_t smb = smem_u32(sm);
    const int tid = threadIdx.x, cta = blockIdx.x;
    const int lane = tid & 31, wid = tid >> 5;
    const int wm = wid & 1, wn = wid >> 1;           // 2m x 4n warps
    const int mtile = cta & 7, ntile = cta >> 3;     // 8 mtiles x 16 ntiles
    const int m0 = mtile * 32;
    const float tauv = __ldg(taup);
    unsigned *mybar = &g_arrm[mtile * 32];

    const int cc = lane & 3;
    const int hbash = ntile * 32 + wn * 8 + (cc >> 1);
    const int mg0 = m0 + wm * 16 + (lane >> 2);

    // ---- fill W slice (n128 x k256, pitch 512B) into U slot, compute pre ----
    {
        char *p = sm;
#pragma unroll
        for (int i = 0; i < 16; ++i) {
            int u = tid + 256 * i, n = u >> 5, kg = u & 31;
            uint32_t d = n * 512 + ((kg * 16) ^ ((n & 7) << 4));
            *(uint4 *)(p + SO_U + d) =
                *(const uint4 *)(g_Wf + (size_t)(ntile * 128 + n) * 256 + kg * 8);
        }
    }
    __syncthreads();

    float C[4][4];
#pragma unroll
    for (int a = 0; a < 4; ++a)
#pragma unroll
        for (int r = 0; r < 4; ++r) C[a][r] = 0.0f;
    run_gemm<1, 512, true>(g_x0h, g_x0l, II, m0, smb, tid, lane, wm, wn, C);

    float pre[4][4];
#pragma unroll
    for (int nb = 0; nb < 4; ++nb)
#pragma unroll
        for (int r = 0; r < 4; ++r) {
            int gate = (cc * 2 + (r & 1)) & 3;
            int hg = ntile * 32 + wn * 8 + nb * 2 + (cc >> 1);
            pre[nb][r] = C[nb][r] + __ldg(Wb + gate * 512 + hg);
        }
    __syncthreads();

    // ---- fill U resident (n128 x k512, pitch 1024B, fp16, 128KB) ----
    {
        char *p = sm;
#pragma unroll
        for (int i = 0; i < 32; ++i) {
            int u = tid + 256 * i, n = u >> 6, kg = u & 63;
            uint32_t d = n * 1024 + ((kg * 16) ^ ((n & 7) << 4));
            *(uint4 *)(p + SO_U + d) =
                *(const uint4 *)(g_Uf + (size_t)(ntile * 128 + n) * 512 + kg * 8);
        }
    }
    __syncthreads();

    // ---- per-thread cell states (4 cells: [p][mh]); fp32 resident all steps ----
    float cs[2][2], hs[2][2];
#pragma unroll
    for (int p = 0; p < 2; ++p) {
        int nb = (lane & 1) ? 2 + p : p;
        int hg = hbash + nb * 2;
#pragma unroll
        for (int mh = 0; mh < 2; ++mh) {
            int mg = mg0 + mh * 8;
            cs[p][mh] = __ldg(c0in + (size_t)mg * 512 + hg);
            hs[p][mh] = __ldg(h0in + (size_t)mg * 512 + hg);
        }
    }

    // ---- time loop: per-mtile barrier groups (16 CTAs each) ----
    for (int t = 0; t < TT; ++t) {
#pragma unroll
        for (int a = 0; a < 4; ++a)
#pragma unroll
            for (int r = 0; r < 4; ++r) C[a][r] = 0.0f;
        run_gemm<2, 1024, false>(g_ah[t & 1], (const __half *)0, HH, m0,
                                 smb, tid, lane, wm, wn, C);

        const int bs = __ldg(bsz + t);

        // gate sums = C + pre; exchange complementary gate pairs with lane^1
        float own[2][4], R[2][4];
#pragma unroll
        for (int p = 0; p < 2; ++p)
#pragma unroll
            for (int r = 0; r < 4; ++r) {
                float lo2 = C[p][r] + pre[p][r];
                float hi2 = C[2 + p][r] + pre[2 + p][r];
                own[p][r] = (lane & 1) ? hi2 : lo2;
                float send = (lane & 1) ? lo2 : hi2;
                R[p][r] = __shfl_xor_sync(0xffffffffu, send, 1);
            }

        float o4[2][2];
#pragma unroll
        for (int p = 0; p < 2; ++p) {
#pragma unroll
            for (int mh = 0; mh < 2; ++mh) {
                float vi, vf, vg, vo;
                if (lane & 1) {
                    vg = own[p][mh * 2]; vo = own[p][mh * 2 + 1];
                    vi = R[p][mh * 2];   vf = R[p][mh * 2 + 1];
                } else {
                    vi = own[p][mh * 2]; vf = own[p][mh * 2 + 1];
                    vg = R[p][mh * 2];   vo = R[p][mh * 2 + 1];
                }
                int mg = mg0 + mh * 8;
                float cn = sigf(vf) * cs[p][mh] + sigf(vi) * tanhfast(vg);
                float hn = sigf(vo) * tanhfast(cn);
                bool act = (mg < bs);
                o4[p][mh] = act ? hn : 0.0f;
                if (act) { cs[p][mh] = cn; hs[p][mh] = hn; }
            }
        }

        if (t < TT - 1) {
            // drift on h dims 0,1 (ntile 0, wn 0, nb 0 → even lanes, cc 0 and 2)
            if (ntile == 0 && wn == 0) {
#pragma unroll
                for (int mh = 0; mh < 2; ++mh) {
                    float mine = hs[0][mh];
                    float oth = __shfl_xor_sync(0xffffffffu, mine, 2);
                    if (!(lane & 1)) {
                        if (cc == 0)
                            hs[0][mh] = mine + tauv * (1.5f * mine + oth * (1.0f / 1.5f));
                        else if (cc == 2)
                            hs[0][mh] = mine - tauv * (1.5f * oth);
                    }
                }
            }
            __half *dh = g_ah[(t + 1) & 1];
#pragma unroll
            for (int p = 0; p < 2; ++p) {
                int nb = (lane & 1) ? 2 + p : p;
                int hg = hbash + nb * 2;
#pragma unroll
                for (int mh = 0; mh < 2; ++mh) {
                    int mg = mg0 + mh * 8;
                    dh[(size_t)mg * 512 + hg] = __float2half_rn(hs[p][mh]);
                }
            }
            // release h writes, arrive; overlap out-stores with barrier wait
            __threadfence();
            __syncthreads();
            if (tid == 0) atomicAdd(mybar, 1u);
#pragma unroll
            for (int p = 0; p < 2; ++p) {
                int nb = (lane & 1) ? 2 + p : p;
                int hg = hbash + nb * 2;
#pragma unroll
                for (int mh = 0; mh < 2; ++mh)
                    out[(size_t)t * BH + (size_t)(mg0 + mh * 8) * 512 + hg] = o4[p][mh];
            }
            if (tid == 0) {
                const unsigned tgt = (unsigned)(t + 1) * 16u;
                while (ldacq(mybar) < tgt) {}
            }
            __syncthreads();
        } else {
#pragma unroll
            for (int p = 0; p < 2; ++p) {
                int nb = (lane & 1) ? 2 + p : p;
                int hg = hbash + nb * 2;
#pragma unroll
                for (int mh = 0; mh < 2; ++mh)
                    out[(size_t)t * BH + (size_t)(mg0 + mh * 8) * 512 + hg] = o4[p][mh];
            }
        }
    }

    // ---- final h, c (from fp32 registers) ----
    const size_t ofs = (size_t)TT * BH;
#pragma unroll
    for (int p = 0; p < 2; ++p) {
        int nb = (lane & 1) ? 2 + p : p;
        int hg = hbash + nb * 2;
#pragma unroll
        for (int mh = 0; mh < 2; ++mh) {
            int mg = mg0 + mh * 8;
            out[ofs + (size_t)mg * 512 + hg] = hs[p][mh];
            out[ofs + BH + (size_t)mg * 512 + hg] = cs[p][mh];
        }
    }
}

extern "C" void kernel_launch(void *const *d_in, const int *in_sizes, int n_in,
                              void *d_out, int out_size)
{
    const float *rnn = (const float *)d_in[0];
    const int *bsz = (const int *)d_in[1];
    const float *h0 = (const float *)d_in[2];
    const float *c0 = (const float *)d_in[3];
    const float *tau = (const float *)d_in[4];
    const float *Ww = (const float *)d_in[5];
    const float *Wb = (const float *)d_in[6];
    const float *Uw = (const float *)d_in[7];
    float *out = (float *)d_out;

    cudaFuncSetAttribute(lstm_mma, cudaFuncAttributeMaxDynamicSharedMemorySize,
                         SMEM_TOT);
    prep_kernel<<<512, 256>>>(rnn, h0, Ww, Uw);
    lstm_mma<<<NCTA, NTHR, SMEM_TOT>>>(bsz, h0, c0, tau, Wb, out);
}